// round 10
// baseline (speedup 1.0000x reference)
#include <cuda_runtime.h>
#include <cuda_bf16.h>
#include <cstdint>

#define NU   50000
#define NPR  20000
#define DU   128
#define Hdim 256
#define OUTD 128
#define NE   800000
#define NPAIR 200000

// ------------------------- scratch (device globals, no allocs) -------------
__device__ float g_hu  [(size_t)NU  * Hdim];
__device__ float g_hp  [(size_t)NPR * Hdim];
__device__ float g_hu1 [(size_t)NU  * Hdim];
__device__ float g_hp1 [(size_t)NPR * Hdim];
__device__ __nv_bfloat16 g_m_u [(size_t)NU  * Hdim];
__device__ __nv_bfloat16 g_m_p [(size_t)NPR * Hdim];
__device__ float g_ng_p[(size_t)NPR * Hdim];
__device__ float g_ng_u[(size_t)NU  * Hdim];

// tf32-rounded copies of the 12 layer weights
__device__ float g_w_l1up_pre [Hdim * Hdim];
__device__ float g_w_l1up_nb  [Hdim * Hdim];
__device__ float g_w_l1up_self[Hdim * Hdim];
__device__ float g_w_l1pu_pre [Hdim * Hdim];
__device__ float g_w_l1pu_nb  [Hdim * Hdim];
__device__ float g_w_l1pu_self[Hdim * Hdim];
__device__ float g_w_l2up_pre [Hdim * Hdim];
__device__ float g_w_l2up_nb  [Hdim * OUTD];
__device__ float g_w_l2up_self[Hdim * OUTD];
__device__ float g_w_l2pu_pre [Hdim * Hdim];
__device__ float g_w_l2pu_nb  [Hdim * OUTD];
__device__ float g_w_l2pu_self[Hdim * OUTD];

__device__ int g_eu_cnt[NPR];
__device__ int g_eu_off[NPR + 1];
__device__ int g_eu_cur[NPR];
__device__ int g_eu_adj[NE];

__device__ int g_ep_cnt[NU];
__device__ int g_ep_off[NU + 1];
__device__ int g_ep_cur[NU];
__device__ int g_ep_adj[NE];

// ---- streams/events created at static init ----
enum { EV_FORK = 0, EV_HP, EV_HU, EV_HP1, EV_HU1, EV_HU2, EV_COUNT };
static cudaStream_t g_s1;
static cudaEvent_t  g_ev[EV_COUNT];
struct InitStreams {
    InitStreams() {
        cudaStreamCreateWithFlags(&g_s1, cudaStreamNonBlocking);
        for (int i = 0; i < EV_COUNT; i++)
            cudaEventCreateWithFlags(&g_ev[i], cudaEventDisableTiming);
    }
};
static InitStreams g_init_streams;

// ------------------------- helpers -----------------------------------------
__device__ __forceinline__ uint32_t f2tf32(float x) {
    uint32_t r;
    asm("cvt.rna.tf32.f32 %0, %1;" : "=r"(r) : "f"(x));
    return r;
}
__device__ __forceinline__ float rnd_tf32(float x) {
    return __uint_as_float(f2tf32(x));
}

// fused tf32-rounding of up to 7 buffers in one launch
struct CvtBatch {
    const float* src[7];
    float*       dst[7];
    int          n4[7];
};
__global__ void cvt_batch_k(CvtBatch b) {
    int y = blockIdx.y;
    int i = blockIdx.x * blockDim.x + threadIdx.x;
    if (i < b.n4[y]) {
        float4 v = reinterpret_cast<const float4*>(b.src[y])[i];
        v.x = rnd_tf32(v.x); v.y = rnd_tf32(v.y);
        v.z = rnd_tf32(v.z); v.w = rnd_tf32(v.w);
        reinterpret_cast<float4*>(b.dst[y])[i] = v;
    }
}

// ------------------------- CSR build ---------------------------------------
__global__ void zero_i_k(int* __restrict__ p, int n) {
    int i = blockIdx.x * blockDim.x + threadIdx.x;
    if (i < n) p[i] = 0;
}

__global__ void count_k(const int* __restrict__ dst, int* __restrict__ cnt, int n) {
    int i = blockIdx.x * blockDim.x + threadIdx.x;
    if (i < n) atomicAdd(&cnt[dst[i]], 1);
}

__global__ void scan_k(const int* __restrict__ cnt, int n,
                       int* __restrict__ off, int* __restrict__ cur) {
    __shared__ int sh[1024];
    __shared__ int carry;
    int tid = threadIdx.x;
    if (tid == 0) carry = 0;
    __syncthreads();
    for (int base = 0; base < n; base += 1024) {
        int i = base + tid;
        int v = (i < n) ? cnt[i] : 0;
        sh[tid] = v;
        __syncthreads();
        for (int d = 1; d < 1024; d <<= 1) {
            int t = (tid >= d) ? sh[tid - d] : 0;
            __syncthreads();
            sh[tid] += t;
            __syncthreads();
        }
        int excl = sh[tid] - v + carry;
        if (i < n) { off[i] = excl; cur[i] = excl; }
        __syncthreads();
        if (tid == 0) carry += sh[1023];
        __syncthreads();
    }
    if (threadIdx.x == 0) off[n] = carry;
}

__global__ void scatter_k(const int* __restrict__ src, const int* __restrict__ dst,
                          int* __restrict__ cur, int* __restrict__ adj, int n) {
    int i = blockIdx.x * blockDim.x + threadIdx.x;
    if (i < n) {
        int pos = atomicAdd(&cur[dst[i]], 1);
        adj[pos] = src[i];
    }
}

// ------------------------- TF32 tensor-core GEMM ---------------------------
// Block tile 128 x BN, BN = MT*32 (MT=4 -> 128x128, 8 warps 2m x 4n, 3-stage,
// 2 CTA/SM; MT=2 -> 128x64, 8 warps 4m x 2n, 2-stage, 3 CTA/SM).
// A fragments via ldmatrix.x4; B fragments via bank-bijective LDS.32.
// CVT: raw fp32 inputs, register-staged loader with cvt.rna (else cp.async).
// NORM: fused relu + row-L2-normalize epilogue (MT==4, N==128, grid.x==1 only)
#define AS_LD 36          // % 32 == 4
#define AS_STAGE (128 * AS_LD)

__device__ __forceinline__ void mma_tf32(float c[4], uint32_t a0, uint32_t a1,
                                         uint32_t a2, uint32_t a3,
                                         uint32_t b0, uint32_t b1) {
    asm volatile(
        "mma.sync.aligned.m16n8k8.row.col.f32.tf32.tf32.f32 "
        "{%0,%1,%2,%3}, {%4,%5,%6,%7}, {%8,%9}, {%0,%1,%2,%3};\n"
        : "+f"(c[0]), "+f"(c[1]), "+f"(c[2]), "+f"(c[3])
        : "r"(a0), "r"(a1), "r"(a2), "r"(a3), "r"(b0), "r"(b1));
}

__device__ __forceinline__ void ldsm_x4(uint32_t f[4], uint32_t saddr) {
    asm volatile("ldmatrix.sync.aligned.m8n8.x4.shared.b16 {%0,%1,%2,%3}, [%4];"
                 : "=r"(f[0]), "=r"(f[1]), "=r"(f[2]), "=r"(f[3]) : "r"(saddr));
}

template <bool BIAS, bool RELU, bool DUAL, bool OUTBF16, bool OUTTF32, bool CVT,
          bool NORM, int MT>
__global__ void __launch_bounds__(256, (MT == 2) ? 3 : 2)
gemm_tc(const float* __restrict__ A0, const float* __restrict__ B0,
        const float* __restrict__ A1, const float* __restrict__ B1,
        const float* __restrict__ bias, void* __restrict__ Cv,
        int M, int N, int K) {
    extern __shared__ uint32_t sm[];

    constexpr int BN   = MT * 32;          // 128 or 64
    constexpr int BS_L = BN + 8;           // 136 or 72; %32==8 -> bijective
    constexpr int BS_STG = 32 * BS_L;
    constexpr int NST  = (MT == 2) ? 2 : 3;
    constexpr int BQ   = BN / 4;           // float4 per B row: 32 or 16
    constexpr int NB   = BQ / 8;           // B float4 per thread: 4 or 2

    const int bm = blockIdx.y * 128;
    const int bn = blockIdx.x * BN;
    const int tid  = threadIdx.x;
    const int lane = tid & 31;
    const int warp = tid >> 5;
    const int g = lane >> 2;
    const int t = lane & 3;
    int wm_, wn_;
    if constexpr (MT == 4) { wm_ = (warp & 1) * 64; wn_ = (warp >> 1) * 32; }
    else                   { wm_ = (warp & 3) * 32; wn_ = (warp >> 2) * 32; }
    const int wm = wm_, wn = wn_;

    const int lm_row = (lane & 7) + ((lane >> 3) & 1) * 8;
    const int lm_col = (lane >> 4) * 4;

    const int tps = K / 32;
    const int ntiles = (DUAL ? 2 : 1) * tps;

    float acc[MT][4][4];
    #pragma unroll
    for (int i = 0; i < MT; i++)
        #pragma unroll
        for (int j = 0; j < 4; j++)
            #pragma unroll
            for (int r = 0; r < 4; r++) acc[i][j][r] = 0.f;

    auto compute_tile = [&](const uint32_t* Asb, const uint32_t* Bsb) {
        const uint32_t a_base = (uint32_t)__cvta_generic_to_shared(
            Asb + (wm + lm_row) * AS_LD + lm_col);
        #pragma unroll
        for (int kk = 0; kk < 4; kk++) {
            const int ko = kk * 8;
            uint32_t af[MT][4];
            #pragma unroll
            for (int mt = 0; mt < MT; mt++)
                ldsm_x4(af[mt], a_base + (uint32_t)((mt * 16 * AS_LD + ko) * 4));
            uint32_t bf[4][2];
            #pragma unroll
            for (int nt = 0; nt < 4; nt++) {
                int n0 = wn + nt * 8;
                bf[nt][0] = Bsb[(ko + t    ) * BS_L + n0 + g];
                bf[nt][1] = Bsb[(ko + t + 4) * BS_L + n0 + g];
            }
            #pragma unroll
            for (int mt = 0; mt < MT; mt++)
                #pragma unroll
                for (int nt = 0; nt < 4; nt++)
                    mma_tf32(acc[mt][nt], af[mt][0], af[mt][1], af[mt][2], af[mt][3],
                             bf[nt][0], bf[nt][1]);
        }
    };

    if constexpr (!CVT) {
        auto issue = [&](int tix) {
            const float* A = A0;
            const float* B = B0;
            int k0 = tix;
            if (DUAL && tix >= tps) { A = A1; B = B1; k0 -= tps; }
            k0 *= 32;
            uint32_t* Asb = sm + (tix % NST) * AS_STAGE;
            uint32_t* Bsb = sm + NST * AS_STAGE + (tix % NST) * BS_STG;
            #pragma unroll
            for (int i = 0; i < 4; i++) {
                int idx = tid + i * 256;
                int r = idx >> 3;
                int c = idx & 7;
                int rr = (bm + r < M) ? (bm + r) : (M - 1);
                int sz = (bm + r < M) ? 16 : 0;
                const float* src = A + (size_t)rr * K + k0 + c * 4;
                uint32_t dst = (uint32_t)__cvta_generic_to_shared(Asb + r * AS_LD + c * 4);
                asm volatile("cp.async.cg.shared.global [%0], [%1], 16, %2;\n"
                             :: "r"(dst), "l"(src), "r"(sz));
            }
            #pragma unroll
            for (int i = 0; i < NB; i++) {
                int idx = tid + i * 256;
                int r = idx / BQ;
                int c = idx % BQ;
                const float* src = B + (size_t)(k0 + r) * N + bn + c * 4;
                uint32_t dst = (uint32_t)__cvta_generic_to_shared(Bsb + r * BS_L + c * 4);
                asm volatile("cp.async.cg.shared.global [%0], [%1], 16;\n"
                             :: "r"(dst), "l"(src));
            }
            asm volatile("cp.async.commit_group;\n" ::: "memory");
        };

        if constexpr (NST == 3) {
            issue(0);
            if (1 < ntiles) issue(1); else asm volatile("cp.async.commit_group;\n" ::: "memory");
            for (int tix = 0; tix < ntiles; tix++) {
                asm volatile("cp.async.wait_group 1;\n" ::: "memory");
                __syncthreads();
                if (tix + 2 < ntiles) issue(tix + 2);
                else asm volatile("cp.async.commit_group;\n" ::: "memory");
                compute_tile(sm + (tix % NST) * AS_STAGE,
                             sm + NST * AS_STAGE + (tix % NST) * BS_STG);
            }
        } else {
            // 2-stage: wait-all at top, prefetch next before compute.
            issue(0);
            for (int tix = 0; tix < ntiles; tix++) {
                asm volatile("cp.async.wait_group 0;\n" ::: "memory");
                __syncthreads();   // stage tix ready; all warps done reading stage tix^1
                if (tix + 1 < ntiles) issue(tix + 1);
                compute_tile(sm + (tix % NST) * AS_STAGE,
                             sm + NST * AS_STAGE + (tix % NST) * BS_STG);
            }
        }
    } else {
        float4 ar[4], br[NB];
        auto load_tile = [&](int tix) {
            const float* A = A0;
            const float* B = B0;
            int k0 = tix;
            if (DUAL && tix >= tps) { A = A1; B = B1; k0 -= tps; }
            k0 *= 32;
            #pragma unroll
            for (int i = 0; i < 4; i++) {
                int idx = tid + i * 256;
                int r = idx >> 3;
                int c = idx & 7;
                ar[i] = make_float4(0.f, 0.f, 0.f, 0.f);
                if (bm + r < M)
                    ar[i] = *reinterpret_cast<const float4*>(A + (size_t)(bm + r) * K + k0 + c * 4);
            }
            #pragma unroll
            for (int i = 0; i < NB; i++) {
                int idx = tid + i * 256;
                int r = idx / BQ;
                int c = idx % BQ;
                br[i] = *reinterpret_cast<const float4*>(B + (size_t)(k0 + r) * N + bn + c * 4);
            }
        };
        auto store_tile = [&](int buf) {
            uint32_t* Asb = sm + buf * AS_STAGE;
            uint32_t* Bsb = sm + NST * AS_STAGE + buf * BS_STG;
            #pragma unroll
            for (int i = 0; i < 4; i++) {
                int idx = tid + i * 256;
                int r = idx >> 3;
                int c = idx & 7;
                uint32_t* p = Asb + r * AS_LD + c * 4;
                p[0] = f2tf32(ar[i].x); p[1] = f2tf32(ar[i].y);
                p[2] = f2tf32(ar[i].z); p[3] = f2tf32(ar[i].w);
            }
            #pragma unroll
            for (int i = 0; i < NB; i++) {
                int idx = tid + i * 256;
                int r = idx / BQ;
                int c = idx % BQ;
                uint32_t* p = Bsb + r * BS_L + c * 4;
                p[0] = f2tf32(br[i].x); p[1] = f2tf32(br[i].y);
                p[2] = f2tf32(br[i].z); p[3] = f2tf32(br[i].w);
            }
        };

        load_tile(0);
        store_tile(0);
        __syncthreads();
        for (int tix = 0; tix < ntiles; tix++) {
            const int buf = tix & 1;
            if (tix + 1 < ntiles) load_tile(tix + 1);
            compute_tile(sm + buf * AS_STAGE,
                         sm + NST * AS_STAGE + buf * BS_STG);
            if (tix + 1 < ntiles) {
                store_tile(buf ^ 1);
                __syncthreads();
            }
        }
    }

    if constexpr (NORM) {
        // fused relu + row-L2-normalize; MT==4, N == 128, CTA owns full rows.
        __syncthreads();
        float* rowsum = reinterpret_cast<float*>(sm);   // [128][4]
        const int nw = warp >> 1;
        const int mh = warp & 1;

        float part[4][2];
        #pragma unroll
        for (int mt = 0; mt < MT; mt++) {
            part[mt][0] = 0.f; part[mt][1] = 0.f;
            #pragma unroll
            for (int nt = 0; nt < 4; nt++) {
                #pragma unroll
                for (int h = 0; h < 2; h++) {
                    float vx = fmaxf(acc[mt][nt][h * 2 + 0], 0.f);
                    float vy = fmaxf(acc[mt][nt][h * 2 + 1], 0.f);
                    part[mt][h] += vx * vx + vy * vy;
                }
            }
        }
        #pragma unroll
        for (int mt = 0; mt < MT; mt++)
            #pragma unroll
            for (int h = 0; h < 2; h++) {
                part[mt][h] += __shfl_xor_sync(0xFFFFFFFFu, part[mt][h], 1);
                part[mt][h] += __shfl_xor_sync(0xFFFFFFFFu, part[mt][h], 2);
            }
        if (t == 0) {
            #pragma unroll
            for (int mt = 0; mt < MT; mt++)
                #pragma unroll
                for (int h = 0; h < 2; h++) {
                    int row = mh * 64 + mt * 16 + h * 8 + g;
                    rowsum[row * 4 + nw] = part[mt][h];
                }
        }
        __syncthreads();

        float* C = (float*)Cv;
        #pragma unroll
        for (int mt = 0; mt < MT; mt++) {
            #pragma unroll
            for (int h = 0; h < 2; h++) {
                int lrow = mh * 64 + mt * 16 + h * 8 + g;
                int r = bm + lrow;
                if (r >= M) continue;
                float s = rowsum[lrow * 4 + 0] + rowsum[lrow * 4 + 1]
                        + rowsum[lrow * 4 + 2] + rowsum[lrow * 4 + 3];
                float inv = (s > 0.f) ? rsqrtf(s) : 1.f;
                #pragma unroll
                for (int nt = 0; nt < 4; nt++) {
                    int col = wn + nt * 8 + t * 2;
                    float vx = fmaxf(acc[mt][nt][h * 2 + 0], 0.f) * inv;
                    float vy = fmaxf(acc[mt][nt][h * 2 + 1], 0.f) * inv;
                    *reinterpret_cast<float2*>(C + (size_t)r * N + col) = make_float2(vx, vy);
                }
            }
        }
        return;
    }

    // ---- standard epilogue ----
    #pragma unroll
    for (int mt = 0; mt < MT; mt++) {
        int r0 = bm + wm + mt * 16 + g;
        #pragma unroll
        for (int nt = 0; nt < 4; nt++) {
            int col = bn + wn + nt * 8 + t * 2;
            float b0 = 0.f, b1 = 0.f;
            if (BIAS) { b0 = bias[col]; b1 = bias[col + 1]; }
            #pragma unroll
            for (int h = 0; h < 2; h++) {
                int r = r0 + h * 8;
                if (r >= M) continue;
                float vx = acc[mt][nt][h * 2 + 0] + b0;
                float vy = acc[mt][nt][h * 2 + 1] + b1;
                if (RELU) { vx = fmaxf(vx, 0.f); vy = fmaxf(vy, 0.f); }
                if (OUTBF16) {
                    __nv_bfloat162* C = (__nv_bfloat162*)Cv;
                    C[((size_t)r * N + col) >> 1] = __float22bfloat162_rn(make_float2(vx, vy));
                } else {
                    if (OUTTF32) { vx = rnd_tf32(vx); vy = rnd_tf32(vy); }
                    float* C = (float*)Cv;
                    *reinterpret_cast<float2*>(C + (size_t)r * N + col) = make_float2(vx, vy);
                }
            }
        }
    }
}

// smem sizes per variant
#define SMB_MT2 (2 * (AS_STAGE + 32 * 72) * 4)
#define SMB_MT4 (3 * (AS_STAGE + 32 * 136) * 4)

// ------------------------- mean aggregation (bf16 in, tf32-rounded out) ----
__global__ void agg_mean_bf16_k(const __nv_bfloat16* __restrict__ feat,
                                const int* __restrict__ off, const int* __restrict__ adj,
                                float* __restrict__ out, int n_dst) {
    int w    = (blockIdx.x * blockDim.x + threadIdx.x) >> 5;
    int lane = threadIdx.x & 31;
    if (w >= n_dst) return;
    int s = off[w], e = off[w + 1];
    float acc[8] = {};
    const size_t loff = (size_t)lane * 8;

    auto accum = [&](uint4 v) {
        const uint32_t u[4] = {v.x, v.y, v.z, v.w};
        #pragma unroll
        for (int j = 0; j < 4; j++) {
            float2 f = __bfloat1622float2(*reinterpret_cast<const __nv_bfloat162*>(&u[j]));
            acc[j * 2 + 0] += f.x;
            acc[j * 2 + 1] += f.y;
        }
    };

    int i = s;
    for (; i + 1 < e; i += 2) {
        int s0 = adj[i], s1 = adj[i + 1];
        uint4 v0 = *reinterpret_cast<const uint4*>(feat + (size_t)s0 * Hdim + loff);
        uint4 v1 = *reinterpret_cast<const uint4*>(feat + (size_t)s1 * Hdim + loff);
        accum(v0);
        accum(v1);
    }
    if (i < e) {
        accum(*reinterpret_cast<const uint4*>(feat + (size_t)adj[i] * Hdim + loff));
    }

    float inv = 1.f / fmaxf((float)(e - s), 1.f);
    #pragma unroll
    for (int j = 0; j < 8; j++) acc[j] = rnd_tf32(acc[j] * inv);
    float* orow = out + (size_t)w * Hdim + loff;
    *reinterpret_cast<float4*>(orow)     = make_float4(acc[0], acc[1], acc[2], acc[3]);
    *reinterpret_cast<float4*>(orow + 4) = make_float4(acc[4], acc[5], acc[6], acc[7]);
}

// ------------------------- relu + row L2-normalize (in place) --------------
template <int W, bool OUTTF32>
__global__ void relu_norm_k(float* __restrict__ buf, int n) {
    int w    = (blockIdx.x * blockDim.x + threadIdx.x) >> 5;
    int lane = threadIdx.x & 31;
    if (w >= n) return;
    float4* row = reinterpret_cast<float4*>(buf + (size_t)w * W);
    constexpr int NV = W / 128;
    float4 v[NV];
    float s = 0.f;
    #pragma unroll
    for (int j = 0; j < NV; j++) {
        v[j] = row[lane + 32 * j];
        v[j].x = fmaxf(v[j].x, 0.f); v[j].y = fmaxf(v[j].y, 0.f);
        v[j].z = fmaxf(v[j].z, 0.f); v[j].w = fmaxf(v[j].w, 0.f);
        s += v[j].x * v[j].x + v[j].y * v[j].y + v[j].z * v[j].z + v[j].w * v[j].w;
    }
    #pragma unroll
    for (int o = 16; o; o >>= 1) s += __shfl_xor_sync(0xFFFFFFFFu, s, o);
    float inv = (s > 0.f) ? rsqrtf(s) : 1.f;
    #pragma unroll
    for (int j = 0; j < NV; j++) {
        v[j].x *= inv; v[j].y *= inv; v[j].z *= inv; v[j].w *= inv;
        if (OUTTF32) {
            v[j].x = rnd_tf32(v[j].x); v[j].y = rnd_tf32(v[j].y);
            v[j].z = rnd_tf32(v[j].z); v[j].w = rnd_tf32(v[j].w);
        }
        row[lane + 32 * j] = v[j];
    }
}

// ------------------------- pair cosine dots (pos+neg fused) ----------------
__global__ void pair_dot2_k(const float* __restrict__ xu, const float* __restrict__ xp,
                            const int* __restrict__ pu, const int* __restrict__ pp,
                            const int* __restrict__ nu, const int* __restrict__ np,
                            float* __restrict__ pos, float* __restrict__ neg, int n) {
    int w    = (blockIdx.x * blockDim.x + threadIdx.x) >> 5;
    int lane = threadIdx.x & 31;
    if (w >= 2 * n) return;
    bool isneg = (w >= n);
    int idx = isneg ? (w - n) : w;
    int u = isneg ? nu[idx] : pu[idx];
    int p = isneg ? np[idx] : pp[idx];
    float4 a = reinterpret_cast<const float4*>(xu + (size_t)u * OUTD)[lane];
    float4 b = reinterpret_cast<const float4*>(xp + (size_t)p * OUTD)[lane];
    float s = a.x * b.x + a.y * b.y + a.z * b.z + a.w * b.w;
    #pragma unroll
    for (int o = 16; o; o >>= 1) s += __shfl_xor_sync(0xFFFFFFFFu, s, o);
    if (lane == 0) {
        if (isneg) neg[idx] = s; else pos[idx] = s;
    }
}

// ------------------------- launch ------------------------------------------
static inline int cdiv(int a, int b) { return (a + b - 1) / b; }

extern "C" void kernel_launch(void* const* d_in, const int* in_sizes, int n_in,
                              void* d_out, int out_size) {
    const float* user_x = (const float*)d_in[0];
    const float* prod_x = (const float*)d_in[1];
    const float* W_ue   = (const float*)d_in[2];
    const float* b_ue   = (const float*)d_in[3];
    const float* W_pe   = (const float*)d_in[4];
    const float* b_pe   = (const float*)d_in[5];
    const float* l1_up_pre  = (const float*)d_in[6];
    const float* l1_up_nb   = (const float*)d_in[7];
    const float* l1_up_self = (const float*)d_in[8];
    const float* l1_pu_pre  = (const float*)d_in[9];
    const float* l1_pu_nb   = (const float*)d_in[10];
    const float* l1_pu_self = (const float*)d_in[11];
    const float* l2_up_pre  = (const float*)d_in[12];
    const float* l2_up_nb   = (const float*)d_in[13];
    const float* l2_up_self = (const float*)d_in[14];
    const float* l2_pu_pre  = (const float*)d_in[15];
    const float* l2_pu_nb   = (const float*)d_in[16];
    const float* l2_pu_self = (const float*)d_in[17];
    const int* eu_src = (const int*)d_in[18];
    const int* eu_dst = (const int*)d_in[19];
    const int* ep_src = (const int*)d_in[20];
    const int* ep_dst = (const int*)d_in[21];
    const int* pos_u  = (const int*)d_in[22];
    const int* pos_p  = (const int*)d_in[23];
    const int* neg_u  = (const int*)d_in[24];
    const int* neg_p  = (const int*)d_in[25];

    float *hu, *hp, *hu1, *hp1, *ng_p, *ng_u;
    __nv_bfloat16 *m_u, *m_p;
    float *w1up_pre, *w1up_nb, *w1up_self, *w1pu_pre, *w1pu_nb, *w1pu_self;
    float *w2up_pre, *w2up_nb, *w2up_self, *w2pu_pre, *w2pu_nb, *w2pu_self;
    int *eu_cnt, *eu_off, *eu_cur, *eu_adj;
    int *ep_cnt, *ep_off, *ep_cur, *ep_adj;
    cudaGetSymbolAddress((void**)&hu,   g_hu);
    cudaGetSymbolAddress((void**)&hp,   g_hp);
    cudaGetSymbolAddress((void**)&hu1,  g_hu1);
    cudaGetSymbolAddress((void**)&hp1,  g_hp1);
    cudaGetSymbolAddress((void**)&m_u,  g_m_u);
    cudaGetSymbolAddress((void**)&m_p,  g_m_p);
    cudaGetSymbolAddress((void**)&ng_p, g_ng_p);
    cudaGetSymbolAddress((void**)&ng_u, g_ng_u);
    cudaGetSymbolAddress((void**)&w1up_pre,  g_w_l1up_pre);
    cudaGetSymbolAddress((void**)&w1up_nb,   g_w_l1up_nb);
    cudaGetSymbolAddress((void**)&w1up_self, g_w_l1up_self);
    cudaGetSymbolAddress((void**)&w1pu_pre,  g_w_l1pu_pre);
    cudaGetSymbolAddress((void**)&w1pu_nb,   g_w_l1pu_nb);
    cudaGetSymbolAddress((void**)&w1pu_self, g_w_l1pu_self);
    cudaGetSymbolAddress((void**)&w2up_pre,  g_w_l2up_pre);
    cudaGetSymbolAddress((void**)&w2up_nb,   g_w_l2up_nb);
    cudaGetSymbolAddress((void**)&w2up_self, g_w_l2up_self);
    cudaGetSymbolAddress((void**)&w2pu_pre,  g_w_l2pu_pre);
    cudaGetSymbolAddress((void**)&w2pu_nb,   g_w_l2pu_nb);
    cudaGetSymbolAddress((void**)&w2pu_self, g_w_l2pu_self);
    cudaGetSymbolAddress((void**)&eu_cnt, g_eu_cnt);
    cudaGetSymbolAddress((void**)&eu_off, g_eu_off);
    cudaGetSymbolAddress((void**)&eu_cur, g_eu_cur);
    cudaGetSymbolAddress((void**)&eu_adj, g_eu_adj);
    cudaGetSymbolAddress((void**)&ep_cnt, g_ep_cnt);
    cudaGetSymbolAddress((void**)&ep_off, g_ep_off);
    cudaGetSymbolAddress((void**)&ep_cur, g_ep_cur);
    cudaGetSymbolAddress((void**)&ep_adj, g_ep_adj);

    // MT=2 variants (heavy, N=256)
    cudaFuncSetAttribute(gemm_tc<true,  false, false, false, true,  true,  false, 2>,
                         cudaFuncAttributeMaxDynamicSharedMemorySize, SMB_MT2);
    cudaFuncSetAttribute(gemm_tc<false, true,  false, true,  false, false, false, 2>,
                         cudaFuncAttributeMaxDynamicSharedMemorySize, SMB_MT2);
    cudaFuncSetAttribute(gemm_tc<false, false, true,  false, false, false, false, 2>,
                         cudaFuncAttributeMaxDynamicSharedMemorySize, SMB_MT2);
    // MT=4 NORM variant (N=128, full-row CTA)
    cudaFuncSetAttribute(gemm_tc<false, false, true,  false, false, false, true, 4>,
                         cudaFuncAttributeMaxDynamicSharedMemorySize, SMB_MT4);

    float* out = (float*)d_out;
    float* hu2 = out;
    float* hp2 = out + (size_t)NU * OUTD;
    float* pos = hp2 + (size_t)NPR * OUTD;
    float* neg = pos + NPAIR;

    cudaStream_t s0 = 0;
    cudaStream_t s1 = g_s1;

    const int GU = cdiv(NU, 128), GP = cdiv(NPR, 128);
    const int HH4 = Hdim * Hdim / 4, HO4 = Hdim * OUTD / 4;

    // ---- fork ----
    cudaEventRecord(g_ev[EV_FORK], s0);
    cudaStreamWaitEvent(s1, g_ev[EV_FORK], 0);

    // ---- fused weight tf32-rounding: one launch per stream ----
    {
        CvtBatch b0;
        b0.src[0] = l1_up_pre;  b0.dst[0] = w1up_pre;  b0.n4[0] = HH4;
        b0.src[1] = l1_up_nb;   b0.dst[1] = w1up_nb;   b0.n4[1] = HH4;
        b0.src[2] = l1_up_self; b0.dst[2] = w1up_self; b0.n4[2] = HH4;
        b0.src[3] = l2_up_pre;  b0.dst[3] = w2up_pre;  b0.n4[3] = HH4;
        b0.src[4] = l2_up_nb;   b0.dst[4] = w2up_nb;   b0.n4[4] = HO4;
        b0.src[5] = l2_up_self; b0.dst[5] = w2up_self; b0.n4[5] = HO4;
        b0.src[6] = l2_up_self; b0.dst[6] = w2up_self; b0.n4[6] = 0;
        cvt_batch_k<<<dim3(cdiv(HH4, 256), 7), 256, 0, s0>>>(b0);

        CvtBatch b1;
        b1.src[0] = l1_pu_pre;  b1.dst[0] = w1pu_pre;  b1.n4[0] = HH4;
        b1.src[1] = l1_pu_nb;   b1.dst[1] = w1pu_nb;   b1.n4[1] = HH4;
        b1.src[2] = l1_pu_self; b1.dst[2] = w1pu_self; b1.n4[2] = HH4;
        b1.src[3] = l2_pu_pre;  b1.dst[3] = w2pu_pre;  b1.n4[3] = HH4;
        b1.src[4] = l2_pu_nb;   b1.dst[4] = w2pu_nb;   b1.n4[4] = HO4;
        b1.src[5] = l2_pu_self; b1.dst[5] = w2pu_self; b1.n4[5] = HO4;
        b1.src[6] = l2_pu_self; b1.dst[6] = w2pu_self; b1.n4[6] = 0;
        cvt_batch_k<<<dim3(cdiv(HH4, 256), 7), 256, 0, s1>>>(b1);
    }

    // ---- projections (raw inputs, CVT path; outputs tf32-rounded) ----
    gemm_tc<true, false, false, false, true, true, false, 2><<<dim3(4, GU), 256, SMB_MT2, s0>>>(user_x, W_ue, nullptr, nullptr, b_ue, hu, NU, Hdim, DU);
    cudaEventRecord(g_ev[EV_HU], s0);
    gemm_tc<true, false, false, false, true, true, false, 2><<<dim3(4, GP), 256, SMB_MT2, s1>>>(prod_x, W_pe, nullptr, nullptr, b_pe, hp, NPR, Hdim, DU);
    cudaEventRecord(g_ev[EV_HP], s1);

    // ---- CSR builds (s0: eu, s1: ep) ----
    zero_i_k<<<cdiv(NPR, 256), 256, 0, s0>>>(eu_cnt, NPR);
    count_k<<<cdiv(NE, 256), 256, 0, s0>>>(eu_dst, eu_cnt, NE);
    scan_k<<<1, 1024, 0, s0>>>(eu_cnt, NPR, eu_off, eu_cur);
    scatter_k<<<cdiv(NE, 256), 256, 0, s0>>>(eu_src, eu_dst, eu_cur, eu_adj, NE);

    zero_i_k<<<cdiv(NU, 256), 256, 0, s1>>>(ep_cnt, NU);
    count_k<<<cdiv(NE, 256), 256, 0, s1>>>(ep_dst, ep_cnt, NE);
    scan_k<<<1, 1024, 0, s1>>>(ep_cnt, NU, ep_off, ep_cur);
    scatter_k<<<cdiv(NE, 256), 256, 0, s1>>>(ep_src, ep_dst, ep_cur, ep_adj, NE);

    // ---- layer 1, up-chain on s0 (dst = products) ----
    gemm_tc<false, true, false, true, false, false, false, 2><<<dim3(4, GU), 256, SMB_MT2, s0>>>(hu, w1up_pre, nullptr, nullptr, nullptr, m_u, NU, Hdim, Hdim);
    agg_mean_bf16_k<<<cdiv(NPR * 32, 256), 256, 0, s0>>>(m_u, eu_off, eu_adj, ng_p, NPR);
    cudaStreamWaitEvent(s0, g_ev[EV_HP], 0);
    gemm_tc<false, false, true, false, false, false, false, 2><<<dim3(4, GP), 256, SMB_MT2, s0>>>(hp, w1up_self, ng_p, w1up_nb, nullptr, hp1, NPR, Hdim, Hdim);
    relu_norm_k<256, true><<<cdiv(NPR * 32, 256), 256, 0, s0>>>(hp1, NPR);
    cudaEventRecord(g_ev[EV_HP1], s0);

    // ---- layer 1, pu-chain on s1 (dst = users) ----
    gemm_tc<false, true, false, true, false, false, false, 2><<<dim3(4, GP), 256, SMB_MT2, s1>>>(hp, w1pu_pre, nullptr, nullptr, nullptr, m_p, NPR, Hdim, Hdim);
    agg_mean_bf16_k<<<cdiv(NU * 32, 256), 256, 0, s1>>>(m_p, ep_off, ep_adj, ng_u, NU);
    cudaStreamWaitEvent(s1, g_ev[EV_HU], 0);
    gemm_tc<false, false, true, false, false, false, false, 2><<<dim3(4, GU), 256, SMB_MT2, s1>>>(hu, w1pu_self, ng_u, w1pu_nb, nullptr, hu1, NU, Hdim, Hdim);
    relu_norm_k<256, true><<<cdiv(NU * 32, 256), 256, 0, s1>>>(hu1, NU);
    cudaEventRecord(g_ev[EV_HU1], s1);

    // ---- layer 2, up-chain on s0 (fused norm epilogue, MT=4) ----
    cudaStreamWaitEvent(s0, g_ev[EV_HU1], 0);
    gemm_tc<false, true, false, true, false, false, false, 2><<<dim3(4, GU), 256, SMB_MT2, s0>>>(hu1, w2up_pre, nullptr, nullptr, nullptr, m_u, NU, Hdim, Hdim);
    agg_mean_bf16_k<<<cdiv(NPR * 32, 256), 256, 0, s0>>>(m_u, eu_off, eu_adj, ng_p, NPR);
    gemm_tc<false, false, true, false, false, false, true, 4><<<dim3(1, GP), 256, SMB_MT4, s0>>>(hp1, w2up_self, ng_p, w2up_nb, nullptr, hp2, NPR, OUTD, Hdim);

    // ---- layer 2, pu-chain on s1 (fused norm epilogue, MT=4) ----
    cudaStreamWaitEvent(s1, g_ev[EV_HP1], 0);
    gemm_tc<false, true, false, true, false, false, false, 2><<<dim3(4, GP), 256, SMB_MT2, s1>>>(hp1, w2pu_pre, nullptr, nullptr, nullptr, m_p, NPR, Hdim, Hdim);
    agg_mean_bf16_k<<<cdiv(NU * 32, 256), 256, 0, s1>>>(m_p, ep_off, ep_adj, ng_u, NU);
    gemm_tc<false, false, true, false, false, false, true, 4><<<dim3(1, GU), 256, SMB_MT4, s1>>>(hu1, w2pu_self, ng_u, w2pu_nb, nullptr, hu2, NU, OUTD, Hdim);
    cudaEventRecord(g_ev[EV_HU2], s1);

    // ---- join + fused pair dots on s0 ----
    cudaStreamWaitEvent(s0, g_ev[EV_HU2], 0);
    pair_dot2_k<<<cdiv(2 * NPAIR * 32, 256), 256, 0, s0>>>(hu2, hp2, pos_u, pos_p, neg_u, neg_p, pos, neg, NPAIR);
}

// round 11
// speedup vs baseline: 1.0032x; 1.0032x over previous
#include <cuda_runtime.h>
#include <cuda_bf16.h>
#include <cstdint>

#define NU   50000
#define NPR  20000
#define DU   128
#define Hdim 256
#define OUTD 128
#define NE   800000
#define NPAIR 200000

// ------------------------- scratch (device globals, no allocs) -------------
__device__ float g_hu  [(size_t)NU  * Hdim];
__device__ float g_hp  [(size_t)NPR * Hdim];
__device__ float g_hu1 [(size_t)NU  * Hdim];
__device__ float g_hp1 [(size_t)NPR * Hdim];
__device__ __nv_bfloat16 g_m_u [(size_t)NU  * Hdim];
__device__ __nv_bfloat16 g_m_p [(size_t)NPR * Hdim];
__device__ float g_ng_p[(size_t)NPR * Hdim];
__device__ float g_ng_u[(size_t)NU  * Hdim];

// tf32-rounded copies of the 12 layer weights
__device__ float g_w_l1up_pre [Hdim * Hdim];
__device__ float g_w_l1up_nb  [Hdim * Hdim];
__device__ float g_w_l1up_self[Hdim * Hdim];
__device__ float g_w_l1pu_pre [Hdim * Hdim];
__device__ float g_w_l1pu_nb  [Hdim * Hdim];
__device__ float g_w_l1pu_self[Hdim * Hdim];
__device__ float g_w_l2up_pre [Hdim * Hdim];
__device__ float g_w_l2up_nb  [Hdim * OUTD];
__device__ float g_w_l2up_self[Hdim * OUTD];
__device__ float g_w_l2pu_pre [Hdim * Hdim];
__device__ float g_w_l2pu_nb  [Hdim * OUTD];
__device__ float g_w_l2pu_self[Hdim * OUTD];

__device__ int g_eu_cnt[NPR];
__device__ int g_eu_off[NPR + 1];
__device__ int g_eu_cur[NPR];
__device__ int g_eu_adj[NE];

__device__ int g_ep_cnt[NU];
__device__ int g_ep_off[NU + 1];
__device__ int g_ep_cur[NU];
__device__ int g_ep_adj[NE];

// ---- streams/events created at static init ----
enum { EV_FORK = 0, EV_HP, EV_HU, EV_HP1, EV_HU1, EV_HU2, EV_COUNT };
static cudaStream_t g_s1;
static cudaEvent_t  g_ev[EV_COUNT];
struct InitStreams {
    InitStreams() {
        cudaStreamCreateWithFlags(&g_s1, cudaStreamNonBlocking);
        for (int i = 0; i < EV_COUNT; i++)
            cudaEventCreateWithFlags(&g_ev[i], cudaEventDisableTiming);
    }
};
static InitStreams g_init_streams;

// ------------------------- helpers -----------------------------------------
__device__ __forceinline__ uint32_t f2tf32(float x) {
    uint32_t r;
    asm("cvt.rna.tf32.f32 %0, %1;" : "=r"(r) : "f"(x));
    return r;
}
__device__ __forceinline__ float rnd_tf32(float x) {
    return __uint_as_float(f2tf32(x));
}

// fused tf32-rounding of up to 7 buffers in one launch
struct CvtBatch {
    const float* src[7];
    float*       dst[7];
    int          n4[7];
};
__global__ void cvt_batch_k(CvtBatch b) {
    int y = blockIdx.y;
    int i = blockIdx.x * blockDim.x + threadIdx.x;
    if (i < b.n4[y]) {
        float4 v = reinterpret_cast<const float4*>(b.src[y])[i];
        v.x = rnd_tf32(v.x); v.y = rnd_tf32(v.y);
        v.z = rnd_tf32(v.z); v.w = rnd_tf32(v.w);
        reinterpret_cast<float4*>(b.dst[y])[i] = v;
    }
}

// ------------------------- CSR build ---------------------------------------
__global__ void zero_i_k(int* __restrict__ p, int n) {
    int i = blockIdx.x * blockDim.x + threadIdx.x;
    if (i < n) p[i] = 0;
}

__global__ void count_k(const int* __restrict__ dst, int* __restrict__ cnt, int n) {
    int i = blockIdx.x * blockDim.x + threadIdx.x;
    if (i < n) atomicAdd(&cnt[dst[i]], 1);
}

// chunked single-block exclusive scan: each thread serially owns a contiguous
// chunk; one 1024-wide block scan of per-thread sums; serial write-back.
// ~21 barriers total (vs ~490 in the strided Hillis-Steele version).
__global__ void scan_k(const int* __restrict__ cnt, int n,
                       int* __restrict__ off, int* __restrict__ cur) {
    __shared__ int sh[1024];
    const int tid = threadIdx.x;
    const int CH = (n + 1023) >> 10;
    const int s = tid * CH;
    const int e = min(s + CH, n);

    int local = 0;
    for (int i = s; i < e; i++) local += cnt[i];
    sh[tid] = local;
    __syncthreads();

    // inclusive Hillis-Steele over 1024 partials
    #pragma unroll
    for (int d = 1; d < 1024; d <<= 1) {
        int t = (tid >= d) ? sh[tid - d] : 0;
        __syncthreads();
        sh[tid] += t;
        __syncthreads();
    }
    int excl = sh[tid] - local;   // exclusive prefix of this thread's chunk
    int total = sh[1023];

    int run = excl;
    for (int i = s; i < e; i++) {
        off[i] = run;
        cur[i] = run;
        run += cnt[i];
    }
    if (tid == 0) off[n] = total;
}

__global__ void scatter_k(const int* __restrict__ src, const int* __restrict__ dst,
                          int* __restrict__ cur, int* __restrict__ adj, int n) {
    int i = blockIdx.x * blockDim.x + threadIdx.x;
    if (i < n) {
        int pos = atomicAdd(&cur[dst[i]], 1);
        adj[pos] = src[i];
    }
}

// ------------------------- TF32 tensor-core GEMM ---------------------------
// 128x128 tile, BK=32, 256 thr = 8 warps (2m x 4n), warp tile 64x32.
// A fragments via ldmatrix.x4; B fragments via bank-bijective LDS.32.
// CVT=false: inputs already tf32-rounded -> 3-stage cp.async pipeline.
// CVT=true : raw fp32 inputs -> 2-stage register-staged loader with cvt.rna.
// NORM     : fused relu + row-L2-normalize epilogue (requires N==128, grid.x==1)
#define BK 32
#define AS_LD 36          // % 32 == 4
#define BS_LD 136         // % 32 == 8  -> B fragment reads bank-bijective
#define AS_STAGE (128 * AS_LD)
#define BS_STAGE (BK * BS_LD)
#define NSTAGE 3
#define GEMM_SMEM_BYTES (NSTAGE * (AS_STAGE + BS_STAGE) * 4)

__device__ __forceinline__ void mma_tf32(float c[4], uint32_t a0, uint32_t a1,
                                         uint32_t a2, uint32_t a3,
                                         uint32_t b0, uint32_t b1) {
    asm volatile(
        "mma.sync.aligned.m16n8k8.row.col.f32.tf32.tf32.f32 "
        "{%0,%1,%2,%3}, {%4,%5,%6,%7}, {%8,%9}, {%0,%1,%2,%3};\n"
        : "+f"(c[0]), "+f"(c[1]), "+f"(c[2]), "+f"(c[3])
        : "r"(a0), "r"(a1), "r"(a2), "r"(a3), "r"(b0), "r"(b1));
}

__device__ __forceinline__ void ldsm_x4(uint32_t f[4], uint32_t saddr) {
    asm volatile("ldmatrix.sync.aligned.m8n8.x4.shared.b16 {%0,%1,%2,%3}, [%4];"
                 : "=r"(f[0]), "=r"(f[1]), "=r"(f[2]), "=r"(f[3]) : "r"(saddr));
}

template <bool BIAS, bool RELU, bool DUAL, bool OUTBF16, bool OUTTF32, bool CVT, bool NORM>
__global__ void __launch_bounds__(256, 2)
gemm_tc(const float* __restrict__ A0, const float* __restrict__ B0,
        const float* __restrict__ A1, const float* __restrict__ B1,
        const float* __restrict__ bias, void* __restrict__ Cv,
        int M, int N, int K) {
    extern __shared__ uint32_t sm[];

    const int bm = blockIdx.y * 128;
    const int bn = blockIdx.x * 128;
    const int tid  = threadIdx.x;
    const int lane = tid & 31;
    const int warp = tid >> 5;
    const int g = lane >> 2;
    const int t = lane & 3;
    const int wm = (warp & 1) * 64;
    const int wn = (warp >> 1) * 32;

    const int lm_row = (lane & 7) + ((lane >> 3) & 1) * 8;
    const int lm_col = (lane >> 4) * 4;

    const int tps = K / BK;
    const int ntiles = (DUAL ? 2 : 1) * tps;

    float acc[4][4][4];
    #pragma unroll
    for (int i = 0; i < 4; i++)
        #pragma unroll
        for (int j = 0; j < 4; j++)
            #pragma unroll
            for (int r = 0; r < 4; r++) acc[i][j][r] = 0.f;

    auto compute_tile = [&](const uint32_t* Asb, const uint32_t* Bsb) {
        const uint32_t a_base = (uint32_t)__cvta_generic_to_shared(
            Asb + (wm + lm_row) * AS_LD + lm_col);
        #pragma unroll
        for (int kk = 0; kk < 4; kk++) {
            const int ko = kk * 8;
            uint32_t af[4][4];
            #pragma unroll
            for (int mt = 0; mt < 4; mt++)
                ldsm_x4(af[mt], a_base + (uint32_t)((mt * 16 * AS_LD + ko) * 4));
            uint32_t bf[4][2];
            #pragma unroll
            for (int nt = 0; nt < 4; nt++) {
                int n0 = wn + nt * 8;
                bf[nt][0] = Bsb[(ko + t    ) * BS_LD + n0 + g];
                bf[nt][1] = Bsb[(ko + t + 4) * BS_LD + n0 + g];
            }
            #pragma unroll
            for (int mt = 0; mt < 4; mt++)
                #pragma unroll
                for (int nt = 0; nt < 4; nt++)
                    mma_tf32(acc[mt][nt], af[mt][0], af[mt][1], af[mt][2], af[mt][3],
                             bf[nt][0], bf[nt][1]);
        }
    };

    if constexpr (!CVT) {
        auto issue = [&](int tix) {
            if (tix < ntiles) {
                const float* A = A0;
                const float* B = B0;
                int k0 = tix;
                if (DUAL && tix >= tps) { A = A1; B = B1; k0 -= tps; }
                k0 *= BK;
                uint32_t* Asb = sm + (tix % NSTAGE) * AS_STAGE;
                uint32_t* Bsb = sm + NSTAGE * AS_STAGE + (tix % NSTAGE) * BS_STAGE;
                #pragma unroll
                for (int i = 0; i < 4; i++) {
                    int idx = tid + i * 256;
                    int r = idx >> 3;
                    int c = idx & 7;
                    int rr = (bm + r < M) ? (bm + r) : (M - 1);
                    int sz = (bm + r < M) ? 16 : 0;
                    const float* src = A + (size_t)rr * K + k0 + c * 4;
                    uint32_t dst = (uint32_t)__cvta_generic_to_shared(Asb + r * AS_LD + c * 4);
                    asm volatile("cp.async.cg.shared.global [%0], [%1], 16, %2;\n"
                                 :: "r"(dst), "l"(src), "r"(sz));
                }
                #pragma unroll
                for (int i = 0; i < 4; i++) {
                    int idx = tid + i * 256;
                    int r = idx >> 5;
                    int c = idx & 31;
                    const float* src = B + (size_t)(k0 + r) * N + bn + c * 4;
                    uint32_t dst = (uint32_t)__cvta_generic_to_shared(Bsb + r * BS_LD + c * 4);
                    asm volatile("cp.async.cg.shared.global [%0], [%1], 16;\n"
                                 :: "r"(dst), "l"(src));
                }
            }
            asm volatile("cp.async.commit_group;\n" ::: "memory");
        };

        issue(0);
        issue(1);
        for (int tix = 0; tix < ntiles; tix++) {
            asm volatile("cp.async.wait_group 1;\n" ::: "memory");
            __syncthreads();
            issue(tix + 2);
            compute_tile(sm + (tix % NSTAGE) * AS_STAGE,
                         sm + NSTAGE * AS_STAGE + (tix % NSTAGE) * BS_STAGE);
        }
    } else {
        float4 ar[4], br[4];
        auto load_tile = [&](int tix) {
            const float* A = A0;
            const float* B = B0;
            int k0 = tix;
            if (DUAL && tix >= tps) { A = A1; B = B1; k0 -= tps; }
            k0 *= BK;
            #pragma unroll
            for (int i = 0; i < 4; i++) {
                int idx = tid + i * 256;
                int r = idx >> 3;
                int c = idx & 7;
                ar[i] = make_float4(0.f, 0.f, 0.f, 0.f);
                if (bm + r < M)
                    ar[i] = *reinterpret_cast<const float4*>(A + (size_t)(bm + r) * K + k0 + c * 4);
            }
            #pragma unroll
            for (int i = 0; i < 4; i++) {
                int idx = tid + i * 256;
                int r = idx >> 5;
                int c = idx & 31;
                br[i] = *reinterpret_cast<const float4*>(B + (size_t)(k0 + r) * N + bn + c * 4);
            }
        };
        auto store_tile = [&](int buf) {
            uint32_t* Asb = sm + buf * AS_STAGE;
            uint32_t* Bsb = sm + NSTAGE * AS_STAGE + buf * BS_STAGE;
            #pragma unroll
            for (int i = 0; i < 4; i++) {
                int idx = tid + i * 256;
                int r = idx >> 3;
                int c = idx & 7;
                uint32_t* p = Asb + r * AS_LD + c * 4;
                p[0] = f2tf32(ar[i].x); p[1] = f2tf32(ar[i].y);
                p[2] = f2tf32(ar[i].z); p[3] = f2tf32(ar[i].w);
            }
            #pragma unroll
            for (int i = 0; i < 4; i++) {
                int idx = tid + i * 256;
                int r = idx >> 5;
                int c = idx & 31;
                uint32_t* p = Bsb + r * BS_LD + c * 4;
                p[0] = f2tf32(br[i].x); p[1] = f2tf32(br[i].y);
                p[2] = f2tf32(br[i].z); p[3] = f2tf32(br[i].w);
            }
        };

        load_tile(0);
        store_tile(0);
        __syncthreads();
        for (int tix = 0; tix < ntiles; tix++) {
            const int buf = tix & 1;
            if (tix + 1 < ntiles) load_tile(tix + 1);
            compute_tile(sm + buf * AS_STAGE,
                         sm + NSTAGE * AS_STAGE + buf * BS_STAGE);
            if (tix + 1 < ntiles) {
                store_tile(buf ^ 1);
                __syncthreads();
            }
        }
    }

    if constexpr (NORM) {
        // fused relu + row-L2-normalize; N == 128, CTA owns full rows.
        __syncthreads();
        float* rowsum = reinterpret_cast<float*>(sm);   // [128][4]
        const int nw = warp >> 1;
        const int mh = warp & 1;

        float part[4][2];
        #pragma unroll
        for (int mt = 0; mt < 4; mt++) {
            part[mt][0] = 0.f; part[mt][1] = 0.f;
            #pragma unroll
            for (int nt = 0; nt < 4; nt++) {
                #pragma unroll
                for (int h = 0; h < 2; h++) {
                    float vx = fmaxf(acc[mt][nt][h * 2 + 0], 0.f);
                    float vy = fmaxf(acc[mt][nt][h * 2 + 1], 0.f);
                    part[mt][h] += vx * vx + vy * vy;
                }
            }
        }
        #pragma unroll
        for (int mt = 0; mt < 4; mt++)
            #pragma unroll
            for (int h = 0; h < 2; h++) {
                part[mt][h] += __shfl_xor_sync(0xFFFFFFFFu, part[mt][h], 1);
                part[mt][h] += __shfl_xor_sync(0xFFFFFFFFu, part[mt][h], 2);
            }
        if (t == 0) {
            #pragma unroll
            for (int mt = 0; mt < 4; mt++)
                #pragma unroll
                for (int h = 0; h < 2; h++) {
                    int row = mh * 64 + mt * 16 + h * 8 + g;
                    rowsum[row * 4 + nw] = part[mt][h];
                }
        }
        __syncthreads();

        float* C = (float*)Cv;
        #pragma unroll
        for (int mt = 0; mt < 4; mt++) {
            #pragma unroll
            for (int h = 0; h < 2; h++) {
                int lrow = mh * 64 + mt * 16 + h * 8 + g;
                int r = bm + lrow;
                if (r >= M) continue;
                float s = rowsum[lrow * 4 + 0] + rowsum[lrow * 4 + 1]
                        + rowsum[lrow * 4 + 2] + rowsum[lrow * 4 + 3];
                float inv = (s > 0.f) ? rsqrtf(s) : 1.f;
                #pragma unroll
                for (int nt = 0; nt < 4; nt++) {
                    int col = wn + nt * 8 + t * 2;
                    float vx = fmaxf(acc[mt][nt][h * 2 + 0], 0.f) * inv;
                    float vy = fmaxf(acc[mt][nt][h * 2 + 1], 0.f) * inv;
                    *reinterpret_cast<float2*>(C + (size_t)r * N + col) = make_float2(vx, vy);
                }
            }
        }
        return;
    }

    // ---- standard epilogue ----
    #pragma unroll
    for (int mt = 0; mt < 4; mt++) {
        int r0 = bm + wm + mt * 16 + g;
        #pragma unroll
        for (int nt = 0; nt < 4; nt++) {
            int col = bn + wn + nt * 8 + t * 2;
            float b0 = 0.f, b1 = 0.f;
            if (BIAS) { b0 = bias[col]; b1 = bias[col + 1]; }
            #pragma unroll
            for (int h = 0; h < 2; h++) {
                int r = r0 + h * 8;
                if (r >= M) continue;
                float vx = acc[mt][nt][h * 2 + 0] + b0;
                float vy = acc[mt][nt][h * 2 + 1] + b1;
                if (RELU) { vx = fmaxf(vx, 0.f); vy = fmaxf(vy, 0.f); }
                if (OUTBF16) {
                    __nv_bfloat162* C = (__nv_bfloat162*)Cv;
                    C[((size_t)r * N + col) >> 1] = __float22bfloat162_rn(make_float2(vx, vy));
                } else {
                    if (OUTTF32) { vx = rnd_tf32(vx); vy = rnd_tf32(vy); }
                    float* C = (float*)Cv;
                    *reinterpret_cast<float2*>(C + (size_t)r * N + col) = make_float2(vx, vy);
                }
            }
        }
    }
}

// ------------------------- mean aggregation (bf16 in, tf32-rounded out) ----
__global__ void agg_mean_bf16_k(const __nv_bfloat16* __restrict__ feat,
                                const int* __restrict__ off, const int* __restrict__ adj,
                                float* __restrict__ out, int n_dst) {
    int w    = (blockIdx.x * blockDim.x + threadIdx.x) >> 5;
    int lane = threadIdx.x & 31;
    if (w >= n_dst) return;
    int s = off[w], e = off[w + 1];
    float acc[8] = {};
    const size_t loff = (size_t)lane * 8;

    auto accum = [&](uint4 v) {
        const uint32_t u[4] = {v.x, v.y, v.z, v.w};
        #pragma unroll
        for (int j = 0; j < 4; j++) {
            float2 f = __bfloat1622float2(*reinterpret_cast<const __nv_bfloat162*>(&u[j]));
            acc[j * 2 + 0] += f.x;
            acc[j * 2 + 1] += f.y;
        }
    };

    int i = s;
    for (; i + 1 < e; i += 2) {
        int s0 = adj[i], s1 = adj[i + 1];
        uint4 v0 = *reinterpret_cast<const uint4*>(feat + (size_t)s0 * Hdim + loff);
        uint4 v1 = *reinterpret_cast<const uint4*>(feat + (size_t)s1 * Hdim + loff);
        accum(v0);
        accum(v1);
    }
    if (i < e) {
        accum(*reinterpret_cast<const uint4*>(feat + (size_t)adj[i] * Hdim + loff));
    }

    float inv = 1.f / fmaxf((float)(e - s), 1.f);
    #pragma unroll
    for (int j = 0; j < 8; j++) acc[j] = rnd_tf32(acc[j] * inv);
    float* orow = out + (size_t)w * Hdim + loff;
    *reinterpret_cast<float4*>(orow)     = make_float4(acc[0], acc[1], acc[2], acc[3]);
    *reinterpret_cast<float4*>(orow + 4) = make_float4(acc[4], acc[5], acc[6], acc[7]);
}

// ------------------------- relu + row L2-normalize (in place) --------------
template <int W, bool OUTTF32>
__global__ void relu_norm_k(float* __restrict__ buf, int n) {
    int w    = (blockIdx.x * blockDim.x + threadIdx.x) >> 5;
    int lane = threadIdx.x & 31;
    if (w >= n) return;
    float4* row = reinterpret_cast<float4*>(buf + (size_t)w * W);
    constexpr int NV = W / 128;
    float4 v[NV];
    float s = 0.f;
    #pragma unroll
    for (int j = 0; j < NV; j++) {
        v[j] = row[lane + 32 * j];
        v[j].x = fmaxf(v[j].x, 0.f); v[j].y = fmaxf(v[j].y, 0.f);
        v[j].z = fmaxf(v[j].z, 0.f); v[j].w = fmaxf(v[j].w, 0.f);
        s += v[j].x * v[j].x + v[j].y * v[j].y + v[j].z * v[j].z + v[j].w * v[j].w;
    }
    #pragma unroll
    for (int o = 16; o; o >>= 1) s += __shfl_xor_sync(0xFFFFFFFFu, s, o);
    float inv = (s > 0.f) ? rsqrtf(s) : 1.f;
    #pragma unroll
    for (int j = 0; j < NV; j++) {
        v[j].x *= inv; v[j].y *= inv; v[j].z *= inv; v[j].w *= inv;
        if (OUTTF32) {
            v[j].x = rnd_tf32(v[j].x); v[j].y = rnd_tf32(v[j].y);
            v[j].z = rnd_tf32(v[j].z); v[j].w = rnd_tf32(v[j].w);
        }
        row[lane + 32 * j] = v[j];
    }
}

// ------------------------- pair cosine dots (pos+neg fused) ----------------
__global__ void pair_dot2_k(const float* __restrict__ xu, const float* __restrict__ xp,
                            const int* __restrict__ pu, const int* __restrict__ pp,
                            const int* __restrict__ nu, const int* __restrict__ np,
                            float* __restrict__ pos, float* __restrict__ neg, int n) {
    int w    = (blockIdx.x * blockDim.x + threadIdx.x) >> 5;
    int lane = threadIdx.x & 31;
    if (w >= 2 * n) return;
    bool isneg = (w >= n);
    int idx = isneg ? (w - n) : w;
    int u = isneg ? nu[idx] : pu[idx];
    int p = isneg ? np[idx] : pp[idx];
    float4 a = reinterpret_cast<const float4*>(xu + (size_t)u * OUTD)[lane];
    float4 b = reinterpret_cast<const float4*>(xp + (size_t)p * OUTD)[lane];
    float s = a.x * b.x + a.y * b.y + a.z * b.z + a.w * b.w;
    #pragma unroll
    for (int o = 16; o; o >>= 1) s += __shfl_xor_sync(0xFFFFFFFFu, s, o);
    if (lane == 0) {
        if (isneg) neg[idx] = s; else pos[idx] = s;
    }
}

// ------------------------- launch ------------------------------------------
static inline int cdiv(int a, int b) { return (a + b - 1) / b; }

extern "C" void kernel_launch(void* const* d_in, const int* in_sizes, int n_in,
                              void* d_out, int out_size) {
    const float* user_x = (const float*)d_in[0];
    const float* prod_x = (const float*)d_in[1];
    const float* W_ue   = (const float*)d_in[2];
    const float* b_ue   = (const float*)d_in[3];
    const float* W_pe   = (const float*)d_in[4];
    const float* b_pe   = (const float*)d_in[5];
    const float* l1_up_pre  = (const float*)d_in[6];
    const float* l1_up_nb   = (const float*)d_in[7];
    const float* l1_up_self = (const float*)d_in[8];
    const float* l1_pu_pre  = (const float*)d_in[9];
    const float* l1_pu_nb   = (const float*)d_in[10];
    const float* l1_pu_self = (const float*)d_in[11];
    const float* l2_up_pre  = (const float*)d_in[12];
    const float* l2_up_nb   = (const float*)d_in[13];
    const float* l2_up_self = (const float*)d_in[14];
    const float* l2_pu_pre  = (const float*)d_in[15];
    const float* l2_pu_nb   = (const float*)d_in[16];
    const float* l2_pu_self = (const float*)d_in[17];
    const int* eu_src = (const int*)d_in[18];
    const int* eu_dst = (const int*)d_in[19];
    const int* ep_src = (const int*)d_in[20];
    const int* ep_dst = (const int*)d_in[21];
    const int* pos_u  = (const int*)d_in[22];
    const int* pos_p  = (const int*)d_in[23];
    const int* neg_u  = (const int*)d_in[24];
    const int* neg_p  = (const int*)d_in[25];

    float *hu, *hp, *hu1, *hp1, *ng_p, *ng_u;
    __nv_bfloat16 *m_u, *m_p;
    float *w1up_pre, *w1up_nb, *w1up_self, *w1pu_pre, *w1pu_nb, *w1pu_self;
    float *w2up_pre, *w2up_nb, *w2up_self, *w2pu_pre, *w2pu_nb, *w2pu_self;
    int *eu_cnt, *eu_off, *eu_cur, *eu_adj;
    int *ep_cnt, *ep_off, *ep_cur, *ep_adj;
    cudaGetSymbolAddress((void**)&hu,   g_hu);
    cudaGetSymbolAddress((void**)&hp,   g_hp);
    cudaGetSymbolAddress((void**)&hu1,  g_hu1);
    cudaGetSymbolAddress((void**)&hp1,  g_hp1);
    cudaGetSymbolAddress((void**)&m_u,  g_m_u);
    cudaGetSymbolAddress((void**)&m_p,  g_m_p);
    cudaGetSymbolAddress((void**)&ng_p, g_ng_p);
    cudaGetSymbolAddress((void**)&ng_u, g_ng_u);
    cudaGetSymbolAddress((void**)&w1up_pre,  g_w_l1up_pre);
    cudaGetSymbolAddress((void**)&w1up_nb,   g_w_l1up_nb);
    cudaGetSymbolAddress((void**)&w1up_self, g_w_l1up_self);
    cudaGetSymbolAddress((void**)&w1pu_pre,  g_w_l1pu_pre);
    cudaGetSymbolAddress((void**)&w1pu_nb,   g_w_l1pu_nb);
    cudaGetSymbolAddress((void**)&w1pu_self, g_w_l1pu_self);
    cudaGetSymbolAddress((void**)&w2up_pre,  g_w_l2up_pre);
    cudaGetSymbolAddress((void**)&w2up_nb,   g_w_l2up_nb);
    cudaGetSymbolAddress((void**)&w2up_self, g_w_l2up_self);
    cudaGetSymbolAddress((void**)&w2pu_pre,  g_w_l2pu_pre);
    cudaGetSymbolAddress((void**)&w2pu_nb,   g_w_l2pu_nb);
    cudaGetSymbolAddress((void**)&w2pu_self, g_w_l2pu_self);
    cudaGetSymbolAddress((void**)&eu_cnt, g_eu_cnt);
    cudaGetSymbolAddress((void**)&eu_off, g_eu_off);
    cudaGetSymbolAddress((void**)&eu_cur, g_eu_cur);
    cudaGetSymbolAddress((void**)&eu_adj, g_eu_adj);
    cudaGetSymbolAddress((void**)&ep_cnt, g_ep_cnt);
    cudaGetSymbolAddress((void**)&ep_off, g_ep_off);
    cudaGetSymbolAddress((void**)&ep_cur, g_ep_cur);
    cudaGetSymbolAddress((void**)&ep_adj, g_ep_adj);

    cudaFuncSetAttribute(gemm_tc<true,  false, false, false, true,  true,  false>,
                         cudaFuncAttributeMaxDynamicSharedMemorySize, GEMM_SMEM_BYTES);
    cudaFuncSetAttribute(gemm_tc<false, true,  false, true,  false, false, false>,
                         cudaFuncAttributeMaxDynamicSharedMemorySize, GEMM_SMEM_BYTES);
    cudaFuncSetAttribute(gemm_tc<false, false, true,  false, false, false, false>,
                         cudaFuncAttributeMaxDynamicSharedMemorySize, GEMM_SMEM_BYTES);
    cudaFuncSetAttribute(gemm_tc<false, false, true,  false, false, false, true>,
                         cudaFuncAttributeMaxDynamicSharedMemorySize, GEMM_SMEM_BYTES);

    float* out = (float*)d_out;
    float* hu2 = out;
    float* hp2 = out + (size_t)NU * OUTD;
    float* pos = hp2 + (size_t)NPR * OUTD;
    float* neg = pos + NPAIR;

    cudaStream_t s0 = 0;
    cudaStream_t s1 = g_s1;

    const int GU = cdiv(NU, 128), GP = cdiv(NPR, 128);
    const int SMB = GEMM_SMEM_BYTES;
    const int HH4 = Hdim * Hdim / 4, HO4 = Hdim * OUTD / 4;

    // ---- fork ----
    cudaEventRecord(g_ev[EV_FORK], s0);
    cudaStreamWaitEvent(s1, g_ev[EV_FORK], 0);

    // ---- fused weight tf32-rounding: one launch per stream ----
    {
        CvtBatch b0;
        b0.src[0] = l1_up_pre;  b0.dst[0] = w1up_pre;  b0.n4[0] = HH4;
        b0.src[1] = l1_up_nb;   b0.dst[1] = w1up_nb;   b0.n4[1] = HH4;
        b0.src[2] = l1_up_self; b0.dst[2] = w1up_self; b0.n4[2] = HH4;
        b0.src[3] = l2_up_pre;  b0.dst[3] = w2up_pre;  b0.n4[3] = HH4;
        b0.src[4] = l2_up_nb;   b0.dst[4] = w2up_nb;   b0.n4[4] = HO4;
        b0.src[5] = l2_up_self; b0.dst[5] = w2up_self; b0.n4[5] = HO4;
        b0.src[6] = l2_up_self; b0.dst[6] = w2up_self; b0.n4[6] = 0;
        cvt_batch_k<<<dim3(cdiv(HH4, 256), 7), 256, 0, s0>>>(b0);

        CvtBatch b1;
        b1.src[0] = l1_pu_pre;  b1.dst[0] = w1pu_pre;  b1.n4[0] = HH4;
        b1.src[1] = l1_pu_nb;   b1.dst[1] = w1pu_nb;   b1.n4[1] = HH4;
        b1.src[2] = l1_pu_self; b1.dst[2] = w1pu_self; b1.n4[2] = HH4;
        b1.src[3] = l2_pu_pre;  b1.dst[3] = w2pu_pre;  b1.n4[3] = HH4;
        b1.src[4] = l2_pu_nb;   b1.dst[4] = w2pu_nb;   b1.n4[4] = HO4;
        b1.src[5] = l2_pu_self; b1.dst[5] = w2pu_self; b1.n4[5] = HO4;
        b1.src[6] = l2_pu_self; b1.dst[6] = w2pu_self; b1.n4[6] = 0;
        cvt_batch_k<<<dim3(cdiv(HH4, 256), 7), 256, 0, s1>>>(b1);
    }

    // ---- projections (raw inputs, CVT path; outputs tf32-rounded) ----
    gemm_tc<true, false, false, false, true, true, false><<<dim3(2, GU), 256, SMB, s0>>>(user_x, W_ue, nullptr, nullptr, b_ue, hu, NU, Hdim, DU);
    cudaEventRecord(g_ev[EV_HU], s0);
    gemm_tc<true, false, false, false, true, true, false><<<dim3(2, GP), 256, SMB, s1>>>(prod_x, W_pe, nullptr, nullptr, b_pe, hp, NPR, Hdim, DU);
    cudaEventRecord(g_ev[EV_HP], s1);

    // ---- CSR builds (s0: eu, s1: ep) ----
    zero_i_k<<<cdiv(NPR, 256), 256, 0, s0>>>(eu_cnt, NPR);
    count_k<<<cdiv(NE, 256), 256, 0, s0>>>(eu_dst, eu_cnt, NE);
    scan_k<<<1, 1024, 0, s0>>>(eu_cnt, NPR, eu_off, eu_cur);
    scatter_k<<<cdiv(NE, 256), 256, 0, s0>>>(eu_src, eu_dst, eu_cur, eu_adj, NE);

    zero_i_k<<<cdiv(NU, 256), 256, 0, s1>>>(ep_cnt, NU);
    count_k<<<cdiv(NE, 256), 256, 0, s1>>>(ep_dst, ep_cnt, NE);
    scan_k<<<1, 1024, 0, s1>>>(ep_cnt, NU, ep_off, ep_cur);
    scatter_k<<<cdiv(NE, 256), 256, 0, s1>>>(ep_src, ep_dst, ep_cur, ep_adj, NE);

    // ---- layer 1, up-chain on s0 (dst = products) ----
    gemm_tc<false, true, false, true, false, false, false><<<dim3(2, GU), 256, SMB, s0>>>(hu, w1up_pre, nullptr, nullptr, nullptr, m_u, NU, Hdim, Hdim);
    agg_mean_bf16_k<<<cdiv(NPR * 32, 256), 256, 0, s0>>>(m_u, eu_off, eu_adj, ng_p, NPR);
    cudaStreamWaitEvent(s0, g_ev[EV_HP], 0);
    gemm_tc<false, false, true, false, false, false, false><<<dim3(2, GP), 256, SMB, s0>>>(hp, w1up_self, ng_p, w1up_nb, nullptr, hp1, NPR, Hdim, Hdim);
    relu_norm_k<256, true><<<cdiv(NPR * 32, 256), 256, 0, s0>>>(hp1, NPR);
    cudaEventRecord(g_ev[EV_HP1], s0);

    // ---- layer 1, pu-chain on s1 (dst = users) ----
    gemm_tc<false, true, false, true, false, false, false><<<dim3(2, GP), 256, SMB, s1>>>(hp, w1pu_pre, nullptr, nullptr, nullptr, m_p, NPR, Hdim, Hdim);
    agg_mean_bf16_k<<<cdiv(NU * 32, 256), 256, 0, s1>>>(m_p, ep_off, ep_adj, ng_u, NU);
    cudaStreamWaitEvent(s1, g_ev[EV_HU], 0);
    gemm_tc<false, false, true, false, false, false, false><<<dim3(2, GU), 256, SMB, s1>>>(hu, w1pu_self, ng_u, w1pu_nb, nullptr, hu1, NU, Hdim, Hdim);
    relu_norm_k<256, true><<<cdiv(NU * 32, 256), 256, 0, s1>>>(hu1, NU);
    cudaEventRecord(g_ev[EV_HU1], s1);

    // ---- layer 2, up-chain on s0 (fused norm epilogue) ----
    cudaStreamWaitEvent(s0, g_ev[EV_HU1], 0);
    gemm_tc<false, true, false, true, false, false, false><<<dim3(2, GU), 256, SMB, s0>>>(hu1, w2up_pre, nullptr, nullptr, nullptr, m_u, NU, Hdim, Hdim);
    agg_mean_bf16_k<<<cdiv(NPR * 32, 256), 256, 0, s0>>>(m_u, eu_off, eu_adj, ng_p, NPR);
    gemm_tc<false, false, true, false, false, false, true><<<dim3(1, GP), 256, SMB, s0>>>(hp1, w2up_self, ng_p, w2up_nb, nullptr, hp2, NPR, OUTD, Hdim);

    // ---- layer 2, pu-chain on s1 (fused norm epilogue) ----
    cudaStreamWaitEvent(s1, g_ev[EV_HP1], 0);
    gemm_tc<false, true, false, true, false, false, false><<<dim3(2, GP), 256, SMB, s1>>>(hp1, w2pu_pre, nullptr, nullptr, nullptr, m_p, NPR, Hdim, Hdim);
    agg_mean_bf16_k<<<cdiv(NU * 32, 256), 256, 0, s1>>>(m_p, ep_off, ep_adj, ng_u, NU);
    gemm_tc<false, false, true, false, false, false, true><<<dim3(1, GU), 256, SMB, s1>>>(hu1, w2pu_self, ng_u, w2pu_nb, nullptr, hu2, NU, OUTD, Hdim);
    cudaEventRecord(g_ev[EV_HU2], s1);

    // ---- join + fused pair dots on s0 ----
    cudaStreamWaitEvent(s0, g_ev[EV_HU2], 0);
    pair_dot2_k<<<cdiv(2 * NPAIR * 32, 256), 256, 0, s0>>>(hu2, hp2, pos_u, pos_p, neg_u, neg_p, pos, neg, NPAIR);
}

// round 12
// speedup vs baseline: 1.1362x; 1.1325x over previous
#include <cuda_runtime.h>
#include <cuda_bf16.h>
#include <cuda_fp16.h>
#include <cstdint>

#define NU   50000
#define NPR  20000
#define DU   128
#define Hdim 256
#define OUTD 128
#define NE   800000
#define NPAIR 200000

// ------------------------- scratch (device globals, no allocs) -------------
__device__ float g_hu  [(size_t)NU  * Hdim];
__device__ float g_hp  [(size_t)NPR * Hdim];
__device__ float g_hu1 [(size_t)NU  * Hdim];
__device__ float g_hp1 [(size_t)NPR * Hdim];
__device__ __nv_bfloat16 g_m_u [(size_t)NU  * Hdim];
__device__ __nv_bfloat16 g_m_p [(size_t)NPR * Hdim];
__device__ float g_ng_p[(size_t)NPR * Hdim];
__device__ float g_ng_u[(size_t)NU  * Hdim];

__device__ int g_eu_cnt[NPR];
__device__ int g_eu_off[NPR + 1];
__device__ int g_eu_cur[NPR];
__device__ int g_eu_adj[NE];

__device__ int g_ep_cnt[NU];
__device__ int g_ep_off[NU + 1];
__device__ int g_ep_cur[NU];
__device__ int g_ep_adj[NE];

// ---- streams/events created at static init ----
enum { EV_FORK = 0, EV_HP, EV_HU, EV_HP1, EV_HU1, EV_HU2, EV_COUNT };
static cudaStream_t g_s1;
static cudaEvent_t  g_ev[EV_COUNT];
struct InitStreams {
    InitStreams() {
        cudaStreamCreateWithFlags(&g_s1, cudaStreamNonBlocking);
        for (int i = 0; i < EV_COUNT; i++)
            cudaEventCreateWithFlags(&g_ev[i], cudaEventDisableTiming);
    }
};
static InitStreams g_init_streams;

// ------------------------- CSR build ---------------------------------------
__global__ void zero_i_k(int* __restrict__ p, int n) {
    int i = blockIdx.x * blockDim.x + threadIdx.x;
    if (i < n) p[i] = 0;
}

__global__ void count_k(const int* __restrict__ dst, int* __restrict__ cnt, int n) {
    int i = blockIdx.x * blockDim.x + threadIdx.x;
    if (i < n) atomicAdd(&cnt[dst[i]], 1);
}

// chunked single-block exclusive scan
__global__ void scan_k(const int* __restrict__ cnt, int n,
                       int* __restrict__ off, int* __restrict__ cur) {
    __shared__ int sh[1024];
    const int tid = threadIdx.x;
    const int CH = (n + 1023) >> 10;
    const int s = tid * CH;
    const int e = min(s + CH, n);

    int local = 0;
    for (int i = s; i < e; i++) local += cnt[i];
    sh[tid] = local;
    __syncthreads();

    #pragma unroll
    for (int d = 1; d < 1024; d <<= 1) {
        int t = (tid >= d) ? sh[tid - d] : 0;
        __syncthreads();
        sh[tid] += t;
        __syncthreads();
    }
    int excl = sh[tid] - local;
    int total = sh[1023];

    int run = excl;
    for (int i = s; i < e; i++) {
        off[i] = run;
        cur[i] = run;
        run += cnt[i];
    }
    if (tid == 0) off[n] = total;
}

__global__ void scatter_k(const int* __restrict__ src, const int* __restrict__ dst,
                          int* __restrict__ cur, int* __restrict__ adj, int n) {
    int i = blockIdx.x * blockDim.x + threadIdx.x;
    if (i < n) {
        int pos = atomicAdd(&cur[dst[i]], 1);
        adj[pos] = src[i];
    }
}

// ------------------------- FP16 tensor-core GEMM ---------------------------
// 128x128 tile, BK=32, 256 thr = 8 warps (2m x 4n), warp tile 64x32.
// fp32 inputs converted to fp16 at smem store (register-staged 2-stage).
// mma.sync.m16n8k16.f32.f16.f16.f32; A via ldmatrix.x4, B via ldmatrix.x4.trans.
// NORM: fused relu + row-L2-normalize epilogue (requires N==128, grid.x==1)
#define BK 32
#define AS_LDH 40            // halves; 80B row stride -> ldmatrix conflict-free
#define BS_LDH 136           // halves; 272B row stride -> trans conflict-free
#define AS_STAGEH (128 * AS_LDH)   // 5120 halves
#define BS_STAGEH (BK * BS_LDH)    // 4352 halves
#define GEMM_SMEM_BYTES ((2 * AS_STAGEH + 2 * BS_STAGEH) * 2)

__device__ __forceinline__ void mma_f16(float c[4], uint32_t a0, uint32_t a1,
                                        uint32_t a2, uint32_t a3,
                                        uint32_t b0, uint32_t b1) {
    asm volatile(
        "mma.sync.aligned.m16n8k16.row.col.f32.f16.f16.f32 "
        "{%0,%1,%2,%3}, {%4,%5,%6,%7}, {%8,%9}, {%0,%1,%2,%3};\n"
        : "+f"(c[0]), "+f"(c[1]), "+f"(c[2]), "+f"(c[3])
        : "r"(a0), "r"(a1), "r"(a2), "r"(a3), "r"(b0), "r"(b1));
}

__device__ __forceinline__ void ldsm_x4(uint32_t f[4], uint32_t saddr) {
    asm volatile("ldmatrix.sync.aligned.m8n8.x4.shared.b16 {%0,%1,%2,%3}, [%4];"
                 : "=r"(f[0]), "=r"(f[1]), "=r"(f[2]), "=r"(f[3]) : "r"(saddr));
}
__device__ __forceinline__ void ldsm_x4_t(uint32_t f[4], uint32_t saddr) {
    asm volatile("ldmatrix.sync.aligned.m8n8.x4.trans.shared.b16 {%0,%1,%2,%3}, [%4];"
                 : "=r"(f[0]), "=r"(f[1]), "=r"(f[2]), "=r"(f[3]) : "r"(saddr));
}

__device__ __forceinline__ uint32_t pack_h2(float x, float y) {
    __half2 h = __floats2half2_rn(x, y);
    return *reinterpret_cast<uint32_t*>(&h);
}

template <bool BIAS, bool RELU, bool DUAL, bool OUTBF16, bool NORM>
__global__ void __launch_bounds__(256, 2)
gemm_tc(const float* __restrict__ A0, const float* __restrict__ B0,
        const float* __restrict__ A1, const float* __restrict__ B1,
        const float* __restrict__ bias, void* __restrict__ Cv,
        int M, int N, int K) {
    extern __shared__ __half smh[];

    const int bm = blockIdx.y * 128;
    const int bn = blockIdx.x * 128;
    const int tid  = threadIdx.x;
    const int lane = tid & 31;
    const int warp = tid >> 5;
    const int g = lane >> 2;
    const int t = lane & 3;
    const int wm = (warp & 1) * 64;
    const int wn = (warp >> 1) * 32;

    // ldmatrix source coords
    const int a_row = lane & 15;            // A: row within 16-row block
    const int a_colh = (lane >> 4) * 8;     // A: k-offset (halves)
    const int b_row = ((lane >> 3) & 1) * 8 + (lane & 7);  // B: k within 16
    const int b_colh = (lane >> 4) * 8;     // B: n-offset (halves)

    const int tps = K / BK;
    const int ntiles = (DUAL ? 2 : 1) * tps;

    float acc[4][4][4];
    #pragma unroll
    for (int i = 0; i < 4; i++)
        #pragma unroll
        for (int j = 0; j < 4; j++)
            #pragma unroll
            for (int r = 0; r < 4; r++) acc[i][j][r] = 0.f;

    auto compute_tile = [&](const __half* Asb, const __half* Bsb) {
        #pragma unroll
        for (int kk = 0; kk < 2; kk++) {     // two k16 steps per BK=32
            const int ko = kk * 16;
            const uint32_t a_base = (uint32_t)__cvta_generic_to_shared(
                Asb + (wm + a_row) * AS_LDH + ko + a_colh);
            uint32_t af[4][4];
            #pragma unroll
            for (int mt = 0; mt < 4; mt++)
                ldsm_x4(af[mt], a_base + (uint32_t)(mt * 16 * AS_LDH * 2));
            uint32_t bq[2][4];
            #pragma unroll
            for (int nb = 0; nb < 2; nb++) {
                uint32_t b_base = (uint32_t)__cvta_generic_to_shared(
                    Bsb + (ko + b_row) * BS_LDH + wn + nb * 16 + b_colh);
                ldsm_x4_t(bq[nb], b_base);
            }
            #pragma unroll
            for (int mt = 0; mt < 4; mt++)
                #pragma unroll
                for (int nt = 0; nt < 4; nt++) {
                    const int nb = nt >> 1, sub = (nt & 1) * 2;
                    mma_f16(acc[mt][nt], af[mt][0], af[mt][1], af[mt][2], af[mt][3],
                            bq[nb][sub], bq[nb][sub + 1]);
                }
        }
    };

    float4 ar[4], br[4];
    auto load_tile = [&](int tix) {
        const float* A = A0;
        const float* B = B0;
        int k0 = tix;
        if (DUAL && tix >= tps) { A = A1; B = B1; k0 -= tps; }
        k0 *= BK;
        #pragma unroll
        for (int i = 0; i < 4; i++) {
            int idx = tid + i * 256;
            int r = idx >> 3;           // 0..127 row
            int c = idx & 7;            // float4 group in BK=32
            ar[i] = make_float4(0.f, 0.f, 0.f, 0.f);
            if (bm + r < M)
                ar[i] = *reinterpret_cast<const float4*>(A + (size_t)(bm + r) * K + k0 + c * 4);
        }
        #pragma unroll
        for (int i = 0; i < 4; i++) {
            int idx = tid + i * 256;
            int r = idx >> 5;           // 0..31 k-row
            int c = idx & 31;           // float4 group in N=128
            br[i] = *reinterpret_cast<const float4*>(B + (size_t)(k0 + r) * N + bn + c * 4);
        }
    };
    auto store_tile = [&](int buf) {
        __half* Asb = smh + buf * AS_STAGEH;
        __half* Bsb = smh + 2 * AS_STAGEH + buf * BS_STAGEH;
        #pragma unroll
        for (int i = 0; i < 4; i++) {
            int idx = tid + i * 256;
            int r = idx >> 3;
            int c = idx & 7;
            uint32_t* p = reinterpret_cast<uint32_t*>(Asb + r * AS_LDH + c * 4);
            p[0] = pack_h2(ar[i].x, ar[i].y);
            p[1] = pack_h2(ar[i].z, ar[i].w);
        }
        #pragma unroll
        for (int i = 0; i < 4; i++) {
            int idx = tid + i * 256;
            int r = idx >> 5;
            int c = idx & 31;
            uint32_t* p = reinterpret_cast<uint32_t*>(Bsb + r * BS_LDH + c * 4);
            p[0] = pack_h2(br[i].x, br[i].y);
            p[1] = pack_h2(br[i].z, br[i].w);
        }
    };

    load_tile(0);
    store_tile(0);
    __syncthreads();
    for (int tix = 0; tix < ntiles; tix++) {
        const int buf = tix & 1;
        if (tix + 1 < ntiles) load_tile(tix + 1);
        compute_tile(smh + buf * AS_STAGEH,
                     smh + 2 * AS_STAGEH + buf * BS_STAGEH);
        if (tix + 1 < ntiles) {
            store_tile(buf ^ 1);
            __syncthreads();
        }
    }

    if constexpr (NORM) {
        // fused relu + row-L2-normalize; N == 128, CTA owns full rows.
        __syncthreads();
        float* rowsum = reinterpret_cast<float*>(smh);   // [128][4]
        const int nw = warp >> 1;
        const int mh = warp & 1;

        float part[4][2];
        #pragma unroll
        for (int mt = 0; mt < 4; mt++) {
            part[mt][0] = 0.f; part[mt][1] = 0.f;
            #pragma unroll
            for (int nt = 0; nt < 4; nt++) {
                #pragma unroll
                for (int h = 0; h < 2; h++) {
                    float vx = fmaxf(acc[mt][nt][h * 2 + 0], 0.f);
                    float vy = fmaxf(acc[mt][nt][h * 2 + 1], 0.f);
                    part[mt][h] += vx * vx + vy * vy;
                }
            }
        }
        #pragma unroll
        for (int mt = 0; mt < 4; mt++)
            #pragma unroll
            for (int h = 0; h < 2; h++) {
                part[mt][h] += __shfl_xor_sync(0xFFFFFFFFu, part[mt][h], 1);
                part[mt][h] += __shfl_xor_sync(0xFFFFFFFFu, part[mt][h], 2);
            }
        if (t == 0) {
            #pragma unroll
            for (int mt = 0; mt < 4; mt++)
                #pragma unroll
                for (int h = 0; h < 2; h++) {
                    int row = mh * 64 + mt * 16 + h * 8 + g;
                    rowsum[row * 4 + nw] = part[mt][h];
                }
        }
        __syncthreads();

        float* C = (float*)Cv;
        #pragma unroll
        for (int mt = 0; mt < 4; mt++) {
            #pragma unroll
            for (int h = 0; h < 2; h++) {
                int lrow = mh * 64 + mt * 16 + h * 8 + g;
                int r = bm + lrow;
                if (r >= M) continue;
                float s = rowsum[lrow * 4 + 0] + rowsum[lrow * 4 + 1]
                        + rowsum[lrow * 4 + 2] + rowsum[lrow * 4 + 3];
                float inv = (s > 0.f) ? rsqrtf(s) : 1.f;
                #pragma unroll
                for (int nt = 0; nt < 4; nt++) {
                    int col = wn + nt * 8 + t * 2;
                    float vx = fmaxf(acc[mt][nt][h * 2 + 0], 0.f) * inv;
                    float vy = fmaxf(acc[mt][nt][h * 2 + 1], 0.f) * inv;
                    *reinterpret_cast<float2*>(C + (size_t)r * N + col) = make_float2(vx, vy);
                }
            }
        }
        return;
    }

    // ---- standard epilogue ----
    #pragma unroll
    for (int mt = 0; mt < 4; mt++) {
        int r0 = bm + wm + mt * 16 + g;
        #pragma unroll
        for (int nt = 0; nt < 4; nt++) {
            int col = bn + wn + nt * 8 + t * 2;
            float b0 = 0.f, b1 = 0.f;
            if (BIAS) { b0 = bias[col]; b1 = bias[col + 1]; }
            #pragma unroll
            for (int h = 0; h < 2; h++) {
                int r = r0 + h * 8;
                if (r >= M) continue;
                float vx = acc[mt][nt][h * 2 + 0] + b0;
                float vy = acc[mt][nt][h * 2 + 1] + b1;
                if (RELU) { vx = fmaxf(vx, 0.f); vy = fmaxf(vy, 0.f); }
                if (OUTBF16) {
                    __nv_bfloat162* C = (__nv_bfloat162*)Cv;
                    C[((size_t)r * N + col) >> 1] = __float22bfloat162_rn(make_float2(vx, vy));
                } else {
                    float* C = (float*)Cv;
                    *reinterpret_cast<float2*>(C + (size_t)r * N + col) = make_float2(vx, vy);
                }
            }
        }
    }
}

// ------------------------- mean aggregation (bf16 in, fp32 out) ------------
__global__ void agg_mean_bf16_k(const __nv_bfloat16* __restrict__ feat,
                                const int* __restrict__ off, const int* __restrict__ adj,
                                float* __restrict__ out, int n_dst) {
    int w    = (blockIdx.x * blockDim.x + threadIdx.x) >> 5;
    int lane = threadIdx.x & 31;
    if (w >= n_dst) return;
    int s = off[w], e = off[w + 1];
    float acc[8] = {};
    const size_t loff = (size_t)lane * 8;

    auto accum = [&](uint4 v) {
        const uint32_t u[4] = {v.x, v.y, v.z, v.w};
        #pragma unroll
        for (int j = 0; j < 4; j++) {
            float2 f = __bfloat1622float2(*reinterpret_cast<const __nv_bfloat162*>(&u[j]));
            acc[j * 2 + 0] += f.x;
            acc[j * 2 + 1] += f.y;
        }
    };

    int i = s;
    for (; i + 1 < e; i += 2) {
        int s0 = adj[i], s1 = adj[i + 1];
        uint4 v0 = *reinterpret_cast<const uint4*>(feat + (size_t)s0 * Hdim + loff);
        uint4 v1 = *reinterpret_cast<const uint4*>(feat + (size_t)s1 * Hdim + loff);
        accum(v0);
        accum(v1);
    }
    if (i < e) {
        accum(*reinterpret_cast<const uint4*>(feat + (size_t)adj[i] * Hdim + loff));
    }

    float inv = 1.f / fmaxf((float)(e - s), 1.f);
    float* orow = out + (size_t)w * Hdim + loff;
    *reinterpret_cast<float4*>(orow)     = make_float4(acc[0] * inv, acc[1] * inv, acc[2] * inv, acc[3] * inv);
    *reinterpret_cast<float4*>(orow + 4) = make_float4(acc[4] * inv, acc[5] * inv, acc[6] * inv, acc[7] * inv);
}

// ------------------------- relu + row L2-normalize (in place) --------------
template <int W>
__global__ void relu_norm_k(float* __restrict__ buf, int n) {
    int w    = (blockIdx.x * blockDim.x + threadIdx.x) >> 5;
    int lane = threadIdx.x & 31;
    if (w >= n) return;
    float4* row = reinterpret_cast<float4*>(buf + (size_t)w * W);
    constexpr int NV = W / 128;
    float4 v[NV];
    float s = 0.f;
    #pragma unroll
    for (int j = 0; j < NV; j++) {
        v[j] = row[lane + 32 * j];
        v[j].x = fmaxf(v[j].x, 0.f); v[j].y = fmaxf(v[j].y, 0.f);
        v[j].z = fmaxf(v[j].z, 0.f); v[j].w = fmaxf(v[j].w, 0.f);
        s += v[j].x * v[j].x + v[j].y * v[j].y + v[j].z * v[j].z + v[j].w * v[j].w;
    }
    #pragma unroll
    for (int o = 16; o; o >>= 1) s += __shfl_xor_sync(0xFFFFFFFFu, s, o);
    float inv = (s > 0.f) ? rsqrtf(s) : 1.f;
    #pragma unroll
    for (int j = 0; j < NV; j++) {
        v[j].x *= inv; v[j].y *= inv; v[j].z *= inv; v[j].w *= inv;
        row[lane + 32 * j] = v[j];
    }
}

// ------------------------- pair cosine dots (pos+neg fused) ----------------
__global__ void pair_dot2_k(const float* __restrict__ xu, const float* __restrict__ xp,
                            const int* __restrict__ pu, const int* __restrict__ pp,
                            const int* __restrict__ nu, const int* __restrict__ np,
                            float* __restrict__ pos, float* __restrict__ neg, int n) {
    int w    = (blockIdx.x * blockDim.x + threadIdx.x) >> 5;
    int lane = threadIdx.x & 31;
    if (w >= 2 * n) return;
    bool isneg = (w >= n);
    int idx = isneg ? (w - n) : w;
    int u = isneg ? nu[idx] : pu[idx];
    int p = isneg ? np[idx] : pp[idx];
    float4 a = reinterpret_cast<const float4*>(xu + (size_t)u * OUTD)[lane];
    float4 b = reinterpret_cast<const float4*>(xp + (size_t)p * OUTD)[lane];
    float s = a.x * b.x + a.y * b.y + a.z * b.z + a.w * b.w;
    #pragma unroll
    for (int o = 16; o; o >>= 1) s += __shfl_xor_sync(0xFFFFFFFFu, s, o);
    if (lane == 0) {
        if (isneg) neg[idx] = s; else pos[idx] = s;
    }
}

// ------------------------- launch ------------------------------------------
static inline int cdiv(int a, int b) { return (a + b - 1) / b; }

extern "C" void kernel_launch(void* const* d_in, const int* in_sizes, int n_in,
                              void* d_out, int out_size) {
    const float* user_x = (const float*)d_in[0];
    const float* prod_x = (const float*)d_in[1];
    const float* W_ue   = (const float*)d_in[2];
    const float* b_ue   = (const float*)d_in[3];
    const float* W_pe   = (const float*)d_in[4];
    const float* b_pe   = (const float*)d_in[5];
    const float* l1_up_pre  = (const float*)d_in[6];
    const float* l1_up_nb   = (const float*)d_in[7];
    const float* l1_up_self = (const float*)d_in[8];
    const float* l1_pu_pre  = (const float*)d_in[9];
    const float* l1_pu_nb   = (const float*)d_in[10];
    const float* l1_pu_self = (const float*)d_in[11];
    const float* l2_up_pre  = (const float*)d_in[12];
    const float* l2_up_nb   = (const float*)d_in[13];
    const float* l2_up_self = (const float*)d_in[14];
    const float* l2_pu_pre  = (const float*)d_in[15];
    const float* l2_pu_nb   = (const float*)d_in[16];
    const float* l2_pu_self = (const float*)d_in[17];
    const int* eu_src = (const int*)d_in[18];
    const int* eu_dst = (const int*)d_in[19];
    const int* ep_src = (const int*)d_in[20];
    const int* ep_dst = (const int*)d_in[21];
    const int* pos_u  = (const int*)d_in[22];
    const int* pos_p  = (const int*)d_in[23];
    const int* neg_u  = (const int*)d_in[24];
    const int* neg_p  = (const int*)d_in[25];

    float *hu, *hp, *hu1, *hp1, *ng_p, *ng_u;
    __nv_bfloat16 *m_u, *m_p;
    int *eu_cnt, *eu_off, *eu_cur, *eu_adj;
    int *ep_cnt, *ep_off, *ep_cur, *ep_adj;
    cudaGetSymbolAddress((void**)&hu,   g_hu);
    cudaGetSymbolAddress((void**)&hp,   g_hp);
    cudaGetSymbolAddress((void**)&hu1,  g_hu1);
    cudaGetSymbolAddress((void**)&hp1,  g_hp1);
    cudaGetSymbolAddress((void**)&m_u,  g_m_u);
    cudaGetSymbolAddress((void**)&m_p,  g_m_p);
    cudaGetSymbolAddress((void**)&ng_p, g_ng_p);
    cudaGetSymbolAddress((void**)&ng_u, g_ng_u);
    cudaGetSymbolAddress((void**)&eu_cnt, g_eu_cnt);
    cudaGetSymbolAddress((void**)&eu_off, g_eu_off);
    cudaGetSymbolAddress((void**)&eu_cur, g_eu_cur);
    cudaGetSymbolAddress((void**)&eu_adj, g_eu_adj);
    cudaGetSymbolAddress((void**)&ep_cnt, g_ep_cnt);
    cudaGetSymbolAddress((void**)&ep_off, g_ep_off);
    cudaGetSymbolAddress((void**)&ep_cur, g_ep_cur);
    cudaGetSymbolAddress((void**)&ep_adj, g_ep_adj);

    cudaFuncSetAttribute(gemm_tc<true,  false, false, false, false>,
                         cudaFuncAttributeMaxDynamicSharedMemorySize, GEMM_SMEM_BYTES);
    cudaFuncSetAttribute(gemm_tc<false, true,  false, true,  false>,
                         cudaFuncAttributeMaxDynamicSharedMemorySize, GEMM_SMEM_BYTES);
    cudaFuncSetAttribute(gemm_tc<false, false, true,  false, false>,
                         cudaFuncAttributeMaxDynamicSharedMemorySize, GEMM_SMEM_BYTES);
    cudaFuncSetAttribute(gemm_tc<false, false, true,  false, true>,
                         cudaFuncAttributeMaxDynamicSharedMemorySize, GEMM_SMEM_BYTES);

    float* out = (float*)d_out;
    float* hu2 = out;
    float* hp2 = out + (size_t)NU * OUTD;
    float* pos = hp2 + (size_t)NPR * OUTD;
    float* neg = pos + NPAIR;

    cudaStream_t s0 = 0;
    cudaStream_t s1 = g_s1;

    const int GU = cdiv(NU, 128), GP = cdiv(NPR, 128);
    const int SMB = GEMM_SMEM_BYTES;

    // ---- fork ----
    cudaEventRecord(g_ev[EV_FORK], s0);
    cudaStreamWaitEvent(s1, g_ev[EV_FORK], 0);

    // ---- projections ----
    gemm_tc<true, false, false, false, false><<<dim3(2, GU), 256, SMB, s0>>>(user_x, W_ue, nullptr, nullptr, b_ue, hu, NU, Hdim, DU);
    cudaEventRecord(g_ev[EV_HU], s0);
    gemm_tc<true, false, false, false, false><<<dim3(2, GP), 256, SMB, s1>>>(prod_x, W_pe, nullptr, nullptr, b_pe, hp, NPR, Hdim, DU);
    cudaEventRecord(g_ev[EV_HP], s1);

    // ---- CSR builds (s0: eu, s1: ep) ----
    zero_i_k<<<cdiv(NPR, 256), 256, 0, s0>>>(eu_cnt, NPR);
    count_k<<<cdiv(NE, 256), 256, 0, s0>>>(eu_dst, eu_cnt, NE);
    scan_k<<<1, 1024, 0, s0>>>(eu_cnt, NPR, eu_off, eu_cur);
    scatter_k<<<cdiv(NE, 256), 256, 0, s0>>>(eu_src, eu_dst, eu_cur, eu_adj, NE);

    zero_i_k<<<cdiv(NU, 256), 256, 0, s1>>>(ep_cnt, NU);
    count_k<<<cdiv(NE, 256), 256, 0, s1>>>(ep_dst, ep_cnt, NE);
    scan_k<<<1, 1024, 0, s1>>>(ep_cnt, NU, ep_off, ep_cur);
    scatter_k<<<cdiv(NE, 256), 256, 0, s1>>>(ep_src, ep_dst, ep_cur, ep_adj, NE);

    // ---- layer 1, up-chain on s0 (dst = products) ----
    gemm_tc<false, true, false, true, false><<<dim3(2, GU), 256, SMB, s0>>>(hu, l1_up_pre, nullptr, nullptr, nullptr, m_u, NU, Hdim, Hdim);
    agg_mean_bf16_k<<<cdiv(NPR * 32, 256), 256, 0, s0>>>(m_u, eu_off, eu_adj, ng_p, NPR);
    cudaStreamWaitEvent(s0, g_ev[EV_HP], 0);
    gemm_tc<false, false, true, false, false><<<dim3(2, GP), 256, SMB, s0>>>(hp, l1_up_self, ng_p, l1_up_nb, nullptr, hp1, NPR, Hdim, Hdim);
    relu_norm_k<256><<<cdiv(NPR * 32, 256), 256, 0, s0>>>(hp1, NPR);
    cudaEventRecord(g_ev[EV_HP1], s0);

    // ---- layer 1, pu-chain on s1 (dst = users) ----
    gemm_tc<false, true, false, true, false><<<dim3(2, GP), 256, SMB, s1>>>(hp, l1_pu_pre, nullptr, nullptr, nullptr, m_p, NPR, Hdim, Hdim);
    agg_mean_bf16_k<<<cdiv(NU * 32, 256), 256, 0, s1>>>(m_p, ep_off, ep_adj, ng_u, NU);
    cudaStreamWaitEvent(s1, g_ev[EV_HU], 0);
    gemm_tc<false, false, true, false, false><<<dim3(2, GU), 256, SMB, s1>>>(hu, l1_pu_self, ng_u, l1_pu_nb, nullptr, hu1, NU, Hdim, Hdim);
    relu_norm_k<256><<<cdiv(NU * 32, 256), 256, 0, s1>>>(hu1, NU);
    cudaEventRecord(g_ev[EV_HU1], s1);

    // ---- layer 2, up-chain on s0 (fused norm epilogue) ----
    cudaStreamWaitEvent(s0, g_ev[EV_HU1], 0);
    gemm_tc<false, true, false, true, false><<<dim3(2, GU), 256, SMB, s0>>>(hu1, l2_up_pre, nullptr, nullptr, nullptr, m_u, NU, Hdim, Hdim);
    agg_mean_bf16_k<<<cdiv(NPR * 32, 256), 256, 0, s0>>>(m_u, eu_off, eu_adj, ng_p, NPR);
    gemm_tc<false, false, true, false, true><<<dim3(1, GP), 256, SMB, s0>>>(hp1, l2_up_self, ng_p, l2_up_nb, nullptr, hp2, NPR, OUTD, Hdim);

    // ---- layer 2, pu-chain on s1 (fused norm epilogue) ----
    cudaStreamWaitEvent(s1, g_ev[EV_HP1], 0);
    gemm_tc<false, true, false, true, false><<<dim3(2, GP), 256, SMB, s1>>>(hp1, l2_pu_pre, nullptr, nullptr, nullptr, m_p, NPR, Hdim, Hdim);
    agg_mean_bf16_k<<<cdiv(NU * 32, 256), 256, 0, s1>>>(m_p, ep_off, ep_adj, ng_u, NU);
    gemm_tc<false, false, true, false, true><<<dim3(1, GU), 256, SMB, s1>>>(hu1, l2_pu_self, ng_u, l2_pu_nb, nullptr, hu2, NU, OUTD, Hdim);
    cudaEventRecord(g_ev[EV_HU2], s1);

    // ---- join + fused pair dots on s0 ----
    cudaStreamWaitEvent(s0, g_ev[EV_HU2], 0);
    pair_dot2_k<<<cdiv(2 * NPAIR * 32, 256), 256, 0, s0>>>(hu2, hp2, pos_u, pos_p, neg_u, neg_p, pos, neg, NPAIR);
}

// round 13
// speedup vs baseline: 1.2819x; 1.1283x over previous
#include <cuda_runtime.h>
#include <cuda_fp16.h>
#include <cstdint>

#define NU   50000
#define NPR  20000
#define DU   128
#define Hdim 256
#define OUTD 128
#define NE   800000
#define NPAIR 200000

// ------------------------- scratch (device globals, no allocs) -------------
__device__ __half g_hu  [(size_t)NU  * Hdim];
__device__ __half g_hp  [(size_t)NPR * Hdim];
__device__ __half g_hu1 [(size_t)NU  * Hdim];
__device__ __half g_hp1 [(size_t)NPR * Hdim];
__device__ __half g_m_u [(size_t)NU  * Hdim];
__device__ __half g_m_p [(size_t)NPR * Hdim];
__device__ __half g_ng_p[(size_t)NPR * Hdim];
__device__ __half g_ng_u[(size_t)NU  * Hdim];

// fp16 copies of the 12 layer weights (pre-converted once per launch)
__device__ __half g_w_l1up_pre [Hdim * Hdim];
__device__ __half g_w_l1up_nb  [Hdim * Hdim];
__device__ __half g_w_l1up_self[Hdim * Hdim];
__device__ __half g_w_l1pu_pre [Hdim * Hdim];
__device__ __half g_w_l1pu_nb  [Hdim * Hdim];
__device__ __half g_w_l1pu_self[Hdim * Hdim];
__device__ __half g_w_l2up_pre [Hdim * Hdim];
__device__ __half g_w_l2up_nb  [Hdim * OUTD];
__device__ __half g_w_l2up_self[Hdim * OUTD];
__device__ __half g_w_l2pu_pre [Hdim * Hdim];
__device__ __half g_w_l2pu_nb  [Hdim * OUTD];
__device__ __half g_w_l2pu_self[Hdim * OUTD];

__device__ int g_eu_cnt[NPR];
__device__ int g_eu_off[NPR + 1];
__device__ int g_eu_cur[NPR];
__device__ int g_eu_adj[NE];

__device__ int g_ep_cnt[NU];
__device__ int g_ep_off[NU + 1];
__device__ int g_ep_cur[NU];
__device__ int g_ep_adj[NE];

// ---- streams/events created at static init ----
enum { EV_FORK = 0, EV_HP, EV_HU, EV_HP1, EV_HU1, EV_HU2, EV_COUNT };
static cudaStream_t g_s1;
static cudaEvent_t  g_ev[EV_COUNT];
struct InitStreams {
    InitStreams() {
        cudaStreamCreateWithFlags(&g_s1, cudaStreamNonBlocking);
        for (int i = 0; i < EV_COUNT; i++)
            cudaEventCreateWithFlags(&g_ev[i], cudaEventDisableTiming);
    }
};
static InitStreams g_init_streams;

// ------------------------- helpers -----------------------------------------
__device__ __forceinline__ uint32_t pack_h2(float x, float y) {
    __half2 h = __floats2half2_rn(x, y);
    return *reinterpret_cast<uint32_t*>(&h);
}

// fused fp32->fp16 conversion of up to 7 buffers in one launch
struct CvtBatch {
    const float* src[7];
    __half*      dst[7];
    int          n4[7];
};
__global__ void cvt_batch_k(CvtBatch b) {
    int y = blockIdx.y;
    int i = blockIdx.x * blockDim.x + threadIdx.x;
    if (i < b.n4[y]) {
        float4 v = reinterpret_cast<const float4*>(b.src[y])[i];
        uint32_t* d = reinterpret_cast<uint32_t*>(b.dst[y] + (size_t)i * 4);
        d[0] = pack_h2(v.x, v.y);
        d[1] = pack_h2(v.z, v.w);
    }
}

// ------------------------- CSR build ---------------------------------------
__global__ void zero_i_k(int* __restrict__ p, int n) {
    int i = blockIdx.x * blockDim.x + threadIdx.x;
    if (i < n) p[i] = 0;
}

__global__ void count_k(const int* __restrict__ dst, int* __restrict__ cnt, int n) {
    int i = blockIdx.x * blockDim.x + threadIdx.x;
    if (i < n) atomicAdd(&cnt[dst[i]], 1);
}

__global__ void scan_k(const int* __restrict__ cnt, int n,
                       int* __restrict__ off, int* __restrict__ cur) {
    __shared__ int sh[1024];
    const int tid = threadIdx.x;
    const int CH = (n + 1023) >> 10;
    const int s = tid * CH;
    const int e = min(s + CH, n);

    int local = 0;
    for (int i = s; i < e; i++) local += cnt[i];
    sh[tid] = local;
    __syncthreads();

    #pragma unroll
    for (int d = 1; d < 1024; d <<= 1) {
        int t = (tid >= d) ? sh[tid - d] : 0;
        __syncthreads();
        sh[tid] += t;
        __syncthreads();
    }
    int excl = sh[tid] - local;
    int total = sh[1023];

    int run = excl;
    for (int i = s; i < e; i++) {
        off[i] = run;
        cur[i] = run;
        run += cnt[i];
    }
    if (tid == 0) off[n] = total;
}

__global__ void scatter_k(const int* __restrict__ src, const int* __restrict__ dst,
                          int* __restrict__ cur, int* __restrict__ adj, int n) {
    int i = blockIdx.x * blockDim.x + threadIdx.x;
    if (i < n) {
        int pos = atomicAdd(&cur[dst[i]], 1);
        adj[pos] = src[i];
    }
}

// ------------------------- FP16 tensor-core GEMM ---------------------------
// 128x128 tile, BK=32, 256 thr = 8 warps (2m x 4n), warp tile 64x32.
// CVT=true : fp32 A/B inputs, register-staged 2-stage loader (projections).
// CVT=false: fp16 A/B inputs, cp.async 3-stage pipeline (all heavy GEMMs).
// mma.sync.m16n8k16; A via ldmatrix.x4, B via ldmatrix.x4.trans.
// OUTF16: write __half C. NORM: fused relu+row-L2-norm (N==128, grid.x==1, fp32 C).
#define BK 32
#define AS_LDH 40
#define BS_LDH 136
#define AS_STAGEH (128 * AS_LDH)
#define BS_STAGEH (BK * BS_LDH)
#define NST 3
#define GEMM_SMEM_BYTES (NST * (AS_STAGEH + BS_STAGEH) * 2)

__device__ __forceinline__ void mma_f16(float c[4], uint32_t a0, uint32_t a1,
                                        uint32_t a2, uint32_t a3,
                                        uint32_t b0, uint32_t b1) {
    asm volatile(
        "mma.sync.aligned.m16n8k16.row.col.f32.f16.f16.f32 "
        "{%0,%1,%2,%3}, {%4,%5,%6,%7}, {%8,%9}, {%0,%1,%2,%3};\n"
        : "+f"(c[0]), "+f"(c[1]), "+f"(c[2]), "+f"(c[3])
        : "r"(a0), "r"(a1), "r"(a2), "r"(a3), "r"(b0), "r"(b1));
}

__device__ __forceinline__ void ldsm_x4(uint32_t f[4], uint32_t saddr) {
    asm volatile("ldmatrix.sync.aligned.m8n8.x4.shared.b16 {%0,%1,%2,%3}, [%4];"
                 : "=r"(f[0]), "=r"(f[1]), "=r"(f[2]), "=r"(f[3]) : "r"(saddr));
}
__device__ __forceinline__ void ldsm_x4_t(uint32_t f[4], uint32_t saddr) {
    asm volatile("ldmatrix.sync.aligned.m8n8.x4.trans.shared.b16 {%0,%1,%2,%3}, [%4];"
                 : "=r"(f[0]), "=r"(f[1]), "=r"(f[2]), "=r"(f[3]) : "r"(saddr));
}

template <bool BIAS, bool RELU, bool DUAL, bool OUTF16, bool CVT, bool NORM>
__global__ void __launch_bounds__(256, 2)
gemm_tc(const void* __restrict__ A0v, const void* __restrict__ B0v,
        const void* __restrict__ A1v, const void* __restrict__ B1v,
        const float* __restrict__ bias, void* __restrict__ Cv,
        int M, int N, int K) {
    extern __shared__ __half smh[];

    const int bm = blockIdx.y * 128;
    const int bn = blockIdx.x * 128;
    const int tid  = threadIdx.x;
    const int lane = tid & 31;
    const int warp = tid >> 5;
    const int g = lane >> 2;
    const int t = lane & 3;
    const int wm = (warp & 1) * 64;
    const int wn = (warp >> 1) * 32;

    const int a_row = lane & 15;
    const int a_colh = (lane >> 4) * 8;
    const int b_row = ((lane >> 3) & 1) * 8 + (lane & 7);
    const int b_colh = (lane >> 4) * 8;

    const int tps = K / BK;
    const int ntiles = (DUAL ? 2 : 1) * tps;

    float acc[4][4][4];
    #pragma unroll
    for (int i = 0; i < 4; i++)
        #pragma unroll
        for (int j = 0; j < 4; j++)
            #pragma unroll
            for (int r = 0; r < 4; r++) acc[i][j][r] = 0.f;

    auto compute_tile = [&](const __half* Asb, const __half* Bsb) {
        #pragma unroll
        for (int kk = 0; kk < 2; kk++) {
            const int ko = kk * 16;
            const uint32_t a_base = (uint32_t)__cvta_generic_to_shared(
                Asb + (wm + a_row) * AS_LDH + ko + a_colh);
            uint32_t af[4][4];
            #pragma unroll
            for (int mt = 0; mt < 4; mt++)
                ldsm_x4(af[mt], a_base + (uint32_t)(mt * 16 * AS_LDH * 2));
            uint32_t bq[2][4];
            #pragma unroll
            for (int nb = 0; nb < 2; nb++) {
                uint32_t b_base = (uint32_t)__cvta_generic_to_shared(
                    Bsb + (ko + b_row) * BS_LDH + wn + nb * 16 + b_colh);
                ldsm_x4_t(bq[nb], b_base);
            }
            #pragma unroll
            for (int mt = 0; mt < 4; mt++)
                #pragma unroll
                for (int nt = 0; nt < 4; nt++) {
                    const int nb = nt >> 1, sub = (nt & 1) * 2;
                    mma_f16(acc[mt][nt], af[mt][0], af[mt][1], af[mt][2], af[mt][3],
                            bq[nb][sub], bq[nb][sub + 1]);
                }
        }
    };

    if constexpr (!CVT) {
        // ---- fp16 inputs, cp.async 3-stage pipeline ----
        auto issue = [&](int tix) {
            if (tix < ntiles) {
                const __half* A = (const __half*)A0v;
                const __half* B = (const __half*)B0v;
                int k0 = tix;
                if (DUAL && tix >= tps) { A = (const __half*)A1v; B = (const __half*)B1v; k0 -= tps; }
                k0 *= BK;
                __half* Asb = smh + (tix % NST) * AS_STAGEH;
                __half* Bsb = smh + NST * AS_STAGEH + (tix % NST) * BS_STAGEH;
                #pragma unroll
                for (int i = 0; i < 2; i++) {
                    int idx = tid + i * 256;
                    int r = idx >> 2;             // 0..127 row (4 chunks/row)
                    int c = idx & 3;              // 16B chunk (8 halves)
                    int rr = (bm + r < M) ? (bm + r) : (M - 1);
                    int sz = (bm + r < M) ? 16 : 0;
                    const __half* src = A + (size_t)rr * K + k0 + c * 8;
                    uint32_t dst = (uint32_t)__cvta_generic_to_shared(Asb + r * AS_LDH + c * 8);
                    asm volatile("cp.async.cg.shared.global [%0], [%1], 16, %2;\n"
                                 :: "r"(dst), "l"(src), "r"(sz));
                }
                #pragma unroll
                for (int i = 0; i < 2; i++) {
                    int idx = tid + i * 256;
                    int r = idx >> 4;             // 0..31 k-row (16 chunks/row)
                    int c = idx & 15;
                    const __half* src = B + (size_t)(k0 + r) * N + bn + c * 8;
                    uint32_t dst = (uint32_t)__cvta_generic_to_shared(Bsb + r * BS_LDH + c * 8);
                    asm volatile("cp.async.cg.shared.global [%0], [%1], 16;\n"
                                 :: "r"(dst), "l"(src));
                }
            }
            asm volatile("cp.async.commit_group;\n" ::: "memory");
        };

        issue(0);
        issue(1);
        for (int tix = 0; tix < ntiles; tix++) {
            asm volatile("cp.async.wait_group 1;\n" ::: "memory");
            __syncthreads();
            issue(tix + 2);
            compute_tile(smh + (tix % NST) * AS_STAGEH,
                         smh + NST * AS_STAGEH + (tix % NST) * BS_STAGEH);
        }
    } else {
        // ---- fp32 inputs, register-staged 2-stage loader (projections) ----
        float4 ar[4], br[4];
        auto load_tile = [&](int tix) {
            const float* A = (const float*)A0v;
            const float* B = (const float*)B0v;
            int k0 = tix * BK;
            #pragma unroll
            for (int i = 0; i < 4; i++) {
                int idx = tid + i * 256;
                int r = idx >> 3;
                int c = idx & 7;
                ar[i] = make_float4(0.f, 0.f, 0.f, 0.f);
                if (bm + r < M)
                    ar[i] = *reinterpret_cast<const float4*>(A + (size_t)(bm + r) * K + k0 + c * 4);
            }
            #pragma unroll
            for (int i = 0; i < 4; i++) {
                int idx = tid + i * 256;
                int r = idx >> 5;
                int c = idx & 31;
                br[i] = *reinterpret_cast<const float4*>(B + (size_t)(k0 + r) * N + bn + c * 4);
            }
        };
        auto store_tile = [&](int buf) {
            __half* Asb = smh + buf * AS_STAGEH;
            __half* Bsb = smh + NST * AS_STAGEH + buf * BS_STAGEH;
            #pragma unroll
            for (int i = 0; i < 4; i++) {
                int idx = tid + i * 256;
                int r = idx >> 3;
                int c = idx & 7;
                uint32_t* p = reinterpret_cast<uint32_t*>(Asb + r * AS_LDH + c * 4);
                p[0] = pack_h2(ar[i].x, ar[i].y);
                p[1] = pack_h2(ar[i].z, ar[i].w);
            }
            #pragma unroll
            for (int i = 0; i < 4; i++) {
                int idx = tid + i * 256;
                int r = idx >> 5;
                int c = idx & 31;
                uint32_t* p = reinterpret_cast<uint32_t*>(Bsb + r * BS_LDH + c * 4);
                p[0] = pack_h2(br[i].x, br[i].y);
                p[1] = pack_h2(br[i].z, br[i].w);
            }
        };

        load_tile(0);
        store_tile(0);
        __syncthreads();
        for (int tix = 0; tix < ntiles; tix++) {
            const int buf = tix & 1;
            if (tix + 1 < ntiles) load_tile(tix + 1);
            compute_tile(smh + buf * AS_STAGEH,
                         smh + NST * AS_STAGEH + buf * BS_STAGEH);
            if (tix + 1 < ntiles) {
                store_tile(buf ^ 1);
                __syncthreads();
            }
        }
    }

    if constexpr (NORM) {
        // fused relu + row-L2-normalize; N == 128, CTA owns full rows; fp32 C.
        __syncthreads();
        float* rowsum = reinterpret_cast<float*>(smh);   // [128][4]
        const int nw = warp >> 1;
        const int mh = warp & 1;

        float part[4][2];
        #pragma unroll
        for (int mt = 0; mt < 4; mt++) {
            part[mt][0] = 0.f; part[mt][1] = 0.f;
            #pragma unroll
            for (int nt = 0; nt < 4; nt++) {
                #pragma unroll
                for (int h = 0; h < 2; h++) {
                    float vx = fmaxf(acc[mt][nt][h * 2 + 0], 0.f);
                    float vy = fmaxf(acc[mt][nt][h * 2 + 1], 0.f);
                    part[mt][h] += vx * vx + vy * vy;
                }
            }
        }
        #pragma unroll
        for (int mt = 0; mt < 4; mt++)
            #pragma unroll
            for (int h = 0; h < 2; h++) {
                part[mt][h] += __shfl_xor_sync(0xFFFFFFFFu, part[mt][h], 1);
                part[mt][h] += __shfl_xor_sync(0xFFFFFFFFu, part[mt][h], 2);
            }
        if (t == 0) {
            #pragma unroll
            for (int mt = 0; mt < 4; mt++)
                #pragma unroll
                for (int h = 0; h < 2; h++) {
                    int row = mh * 64 + mt * 16 + h * 8 + g;
                    rowsum[row * 4 + nw] = part[mt][h];
                }
        }
        __syncthreads();

        float* C = (float*)Cv;
        #pragma unroll
        for (int mt = 0; mt < 4; mt++) {
            #pragma unroll
            for (int h = 0; h < 2; h++) {
                int lrow = mh * 64 + mt * 16 + h * 8 + g;
                int r = bm + lrow;
                if (r >= M) continue;
                float s = rowsum[lrow * 4 + 0] + rowsum[lrow * 4 + 1]
                        + rowsum[lrow * 4 + 2] + rowsum[lrow * 4 + 3];
                float inv = (s > 0.f) ? rsqrtf(s) : 1.f;
                #pragma unroll
                for (int nt = 0; nt < 4; nt++) {
                    int col = wn + nt * 8 + t * 2;
                    float vx = fmaxf(acc[mt][nt][h * 2 + 0], 0.f) * inv;
                    float vy = fmaxf(acc[mt][nt][h * 2 + 1], 0.f) * inv;
                    *reinterpret_cast<float2*>(C + (size_t)r * N + col) = make_float2(vx, vy);
                }
            }
        }
        return;
    }

    // ---- standard epilogue ----
    #pragma unroll
    for (int mt = 0; mt < 4; mt++) {
        int r0 = bm + wm + mt * 16 + g;
        #pragma unroll
        for (int nt = 0; nt < 4; nt++) {
            int col = bn + wn + nt * 8 + t * 2;
            float b0 = 0.f, b1 = 0.f;
            if (BIAS) { b0 = bias[col]; b1 = bias[col + 1]; }
            #pragma unroll
            for (int h = 0; h < 2; h++) {
                int r = r0 + h * 8;
                if (r >= M) continue;
                float vx = acc[mt][nt][h * 2 + 0] + b0;
                float vy = acc[mt][nt][h * 2 + 1] + b1;
                if (RELU) { vx = fmaxf(vx, 0.f); vy = fmaxf(vy, 0.f); }
                if (OUTF16) {
                    __half* C = (__half*)Cv;
                    *reinterpret_cast<uint32_t*>(C + (size_t)r * N + col) = pack_h2(vx, vy);
                } else {
                    float* C = (float*)Cv;
                    *reinterpret_cast<float2*>(C + (size_t)r * N + col) = make_float2(vx, vy);
                }
            }
        }
    }
}

// ------------------------- mean aggregation (fp16 in, fp16 out) ------------
__global__ void agg_mean_h_k(const __half* __restrict__ feat,
                             const int* __restrict__ off, const int* __restrict__ adj,
                             __half* __restrict__ out, int n_dst) {
    int w    = (blockIdx.x * blockDim.x + threadIdx.x) >> 5;
    int lane = threadIdx.x & 31;
    if (w >= n_dst) return;
    int s = off[w], e = off[w + 1];
    float acc[8] = {};
    const size_t loff = (size_t)lane * 8;

    auto accum = [&](uint4 v) {
        const uint32_t u[4] = {v.x, v.y, v.z, v.w};
        #pragma unroll
        for (int j = 0; j < 4; j++) {
            float2 f = __half22float2(*reinterpret_cast<const __half2*>(&u[j]));
            acc[j * 2 + 0] += f.x;
            acc[j * 2 + 1] += f.y;
        }
    };

    int i = s;
    for (; i + 1 < e; i += 2) {
        int s0 = adj[i], s1 = adj[i + 1];
        uint4 v0 = *reinterpret_cast<const uint4*>(feat + (size_t)s0 * Hdim + loff);
        uint4 v1 = *reinterpret_cast<const uint4*>(feat + (size_t)s1 * Hdim + loff);
        accum(v0);
        accum(v1);
    }
    if (i < e) {
        accum(*reinterpret_cast<const uint4*>(feat + (size_t)adj[i] * Hdim + loff));
    }

    float inv = 1.f / fmaxf((float)(e - s), 1.f);
    uint4 o;
    uint32_t* ow = reinterpret_cast<uint32_t*>(&o);
    #pragma unroll
    for (int j = 0; j < 4; j++)
        ow[j] = pack_h2(acc[j * 2] * inv, acc[j * 2 + 1] * inv);
    *reinterpret_cast<uint4*>(out + (size_t)w * Hdim + loff) = o;
}

// ------------------------- relu + row L2-normalize (fp16, in place) --------
__global__ void relu_norm_h_k(__half* __restrict__ buf, int n) {
    int w    = (blockIdx.x * blockDim.x + threadIdx.x) >> 5;
    int lane = threadIdx.x & 31;
    if (w >= n) return;
    __half* row = buf + (size_t)w * Hdim;
    uint4 v = *reinterpret_cast<const uint4*>(row + lane * 8);
    uint32_t* vw = reinterpret_cast<uint32_t*>(&v);
    float f[8];
    float s = 0.f;
    #pragma unroll
    for (int j = 0; j < 4; j++) {
        float2 p = __half22float2(*reinterpret_cast<const __half2*>(&vw[j]));
        f[j * 2 + 0] = fmaxf(p.x, 0.f);
        f[j * 2 + 1] = fmaxf(p.y, 0.f);
        s += f[j * 2] * f[j * 2] + f[j * 2 + 1] * f[j * 2 + 1];
    }
    #pragma unroll
    for (int o = 16; o; o >>= 1) s += __shfl_xor_sync(0xFFFFFFFFu, s, o);
    float inv = (s > 0.f) ? rsqrtf(s) : 1.f;
    #pragma unroll
    for (int j = 0; j < 4; j++)
        vw[j] = pack_h2(f[j * 2] * inv, f[j * 2 + 1] * inv);
    *reinterpret_cast<uint4*>(row + lane * 8) = v;
}

// ------------------------- pair cosine dots (pos+neg fused) ----------------
__global__ void pair_dot2_k(const float* __restrict__ xu, const float* __restrict__ xp,
                            const int* __restrict__ pu, const int* __restrict__ pp,
                            const int* __restrict__ nu, const int* __restrict__ np,
                            float* __restrict__ pos, float* __restrict__ neg, int n) {
    int w    = (blockIdx.x * blockDim.x + threadIdx.x) >> 5;
    int lane = threadIdx.x & 31;
    if (w >= 2 * n) return;
    bool isneg = (w >= n);
    int idx = isneg ? (w - n) : w;
    int u = isneg ? nu[idx] : pu[idx];
    int p = isneg ? np[idx] : pp[idx];
    float4 a = reinterpret_cast<const float4*>(xu + (size_t)u * OUTD)[lane];
    float4 b = reinterpret_cast<const float4*>(xp + (size_t)p * OUTD)[lane];
    float s = a.x * b.x + a.y * b.y + a.z * b.z + a.w * b.w;
    #pragma unroll
    for (int o = 16; o; o >>= 1) s += __shfl_xor_sync(0xFFFFFFFFu, s, o);
    if (lane == 0) {
        if (isneg) neg[idx] = s; else pos[idx] = s;
    }
}

// ------------------------- launch ------------------------------------------
static inline int cdiv(int a, int b) { return (a + b - 1) / b; }

extern "C" void kernel_launch(void* const* d_in, const int* in_sizes, int n_in,
                              void* d_out, int out_size) {
    const float* user_x = (const float*)d_in[0];
    const float* prod_x = (const float*)d_in[1];
    const float* W_ue   = (const float*)d_in[2];
    const float* b_ue   = (const float*)d_in[3];
    const float* W_pe   = (const float*)d_in[4];
    const float* b_pe   = (const float*)d_in[5];
    const float* l1_up_pre  = (const float*)d_in[6];
    const float* l1_up_nb   = (const float*)d_in[7];
    const float* l1_up_self = (const float*)d_in[8];
    const float* l1_pu_pre  = (const float*)d_in[9];
    const float* l1_pu_nb   = (const float*)d_in[10];
    const float* l1_pu_self = (const float*)d_in[11];
    const float* l2_up_pre  = (const float*)d_in[12];
    const float* l2_up_nb   = (const float*)d_in[13];
    const float* l2_up_self = (const float*)d_in[14];
    const float* l2_pu_pre  = (const float*)d_in[15];
    const float* l2_pu_nb   = (const float*)d_in[16];
    const float* l2_pu_self = (const float*)d_in[17];
    const int* eu_src = (const int*)d_in[18];
    const int* eu_dst = (const int*)d_in[19];
    const int* ep_src = (const int*)d_in[20];
    const int* ep_dst = (const int*)d_in[21];
    const int* pos_u  = (const int*)d_in[22];
    const int* pos_p  = (const int*)d_in[23];
    const int* neg_u  = (const int*)d_in[24];
    const int* neg_p  = (const int*)d_in[25];

    __half *hu, *hp, *hu1, *hp1, *m_u, *m_p, *ng_p, *ng_u;
    __half *w1up_pre, *w1up_nb, *w1up_self, *w1pu_pre, *w1pu_nb, *w1pu_self;
    __half *w2up_pre, *w2up_nb, *w2up_self, *w2pu_pre, *w2pu_nb, *w2pu_self;
    int *eu_cnt, *eu_off, *eu_cur, *eu_adj;
    int *ep_cnt, *ep_off, *ep_cur, *ep_adj;
    cudaGetSymbolAddress((void**)&hu,   g_hu);
    cudaGetSymbolAddress((void**)&hp,   g_hp);
    cudaGetSymbolAddress((void**)&hu1,  g_hu1);
    cudaGetSymbolAddress((void**)&hp1,  g_hp1);
    cudaGetSymbolAddress((void**)&m_u,  g_m_u);
    cudaGetSymbolAddress((void**)&m_p,  g_m_p);
    cudaGetSymbolAddress((void**)&ng_p, g_ng_p);
    cudaGetSymbolAddress((void**)&ng_u, g_ng_u);
    cudaGetSymbolAddress((void**)&w1up_pre,  g_w_l1up_pre);
    cudaGetSymbolAddress((void**)&w1up_nb,   g_w_l1up_nb);
    cudaGetSymbolAddress((void**)&w1up_self, g_w_l1up_self);
    cudaGetSymbolAddress((void**)&w1pu_pre,  g_w_l1pu_pre);
    cudaGetSymbolAddress((void**)&w1pu_nb,   g_w_l1pu_nb);
    cudaGetSymbolAddress((void**)&w1pu_self, g_w_l1pu_self);
    cudaGetSymbolAddress((void**)&w2up_pre,  g_w_l2up_pre);
    cudaGetSymbolAddress((void**)&w2up_nb,   g_w_l2up_nb);
    cudaGetSymbolAddress((void**)&w2up_self, g_w_l2up_self);
    cudaGetSymbolAddress((void**)&w2pu_pre,  g_w_l2pu_pre);
    cudaGetSymbolAddress((void**)&w2pu_nb,   g_w_l2pu_nb);
    cudaGetSymbolAddress((void**)&w2pu_self, g_w_l2pu_self);
    cudaGetSymbolAddress((void**)&eu_cnt, g_eu_cnt);
    cudaGetSymbolAddress((void**)&eu_off, g_eu_off);
    cudaGetSymbolAddress((void**)&eu_cur, g_eu_cur);
    cudaGetSymbolAddress((void**)&eu_adj, g_eu_adj);
    cudaGetSymbolAddress((void**)&ep_cnt, g_ep_cnt);
    cudaGetSymbolAddress((void**)&ep_off, g_ep_off);
    cudaGetSymbolAddress((void**)&ep_cur, g_ep_cur);
    cudaGetSymbolAddress((void**)&ep_adj, g_ep_adj);

    cudaFuncSetAttribute(gemm_tc<true,  false, false, true,  true,  false>,
                         cudaFuncAttributeMaxDynamicSharedMemorySize, GEMM_SMEM_BYTES);
    cudaFuncSetAttribute(gemm_tc<false, true,  false, true,  false, false>,
                         cudaFuncAttributeMaxDynamicSharedMemorySize, GEMM_SMEM_BYTES);
    cudaFuncSetAttribute(gemm_tc<false, false, true,  true,  false, false>,
                         cudaFuncAttributeMaxDynamicSharedMemorySize, GEMM_SMEM_BYTES);
    cudaFuncSetAttribute(gemm_tc<false, false, true,  false, false, true>,
                         cudaFuncAttributeMaxDynamicSharedMemorySize, GEMM_SMEM_BYTES);

    float* out = (float*)d_out;
    float* hu2 = out;
    float* hp2 = out + (size_t)NU * OUTD;
    float* pos = hp2 + (size_t)NPR * OUTD;
    float* neg = pos + NPAIR;

    cudaStream_t s0 = 0;
    cudaStream_t s1 = g_s1;

    const int GU = cdiv(NU, 128), GP = cdiv(NPR, 128);
    const int SMB = GEMM_SMEM_BYTES;
    const int HH4 = Hdim * Hdim / 4, HO4 = Hdim * OUTD / 4;

    // ---- fork ----
    cudaEventRecord(g_ev[EV_FORK], s0);
    cudaStreamWaitEvent(s1, g_ev[EV_FORK], 0);

    // ---- fused weight fp16 conversion: one launch per stream ----
    {
        CvtBatch b0;
        b0.src[0] = l1_up_pre;  b0.dst[0] = w1up_pre;  b0.n4[0] = HH4;
        b0.src[1] = l1_up_nb;   b0.dst[1] = w1up_nb;   b0.n4[1] = HH4;
        b0.src[2] = l1_up_self; b0.dst[2] = w1up_self; b0.n4[2] = HH4;
        b0.src[3] = l2_up_pre;  b0.dst[3] = w2up_pre;  b0.n4[3] = HH4;
        b0.src[4] = l2_up_nb;   b0.dst[4] = w2up_nb;   b0.n4[4] = HO4;
        b0.src[5] = l2_up_self; b0.dst[5] = w2up_self; b0.n4[5] = HO4;
        b0.src[6] = l2_up_self; b0.dst[6] = w2up_self; b0.n4[6] = 0;
        cvt_batch_k<<<dim3(cdiv(HH4, 256), 7), 256, 0, s0>>>(b0);

        CvtBatch b1;
        b1.src[0] = l1_pu_pre;  b1.dst[0] = w1pu_pre;  b1.n4[0] = HH4;
        b1.src[1] = l1_pu_nb;   b1.dst[1] = w1pu_nb;   b1.n4[1] = HH4;
        b1.src[2] = l1_pu_self; b1.dst[2] = w1pu_self; b1.n4[2] = HH4;
        b1.src[3] = l2_pu_pre;  b1.dst[3] = w2pu_pre;  b1.n4[3] = HH4;
        b1.src[4] = l2_pu_nb;   b1.dst[4] = w2pu_nb;   b1.n4[4] = HO4;
        b1.src[5] = l2_pu_self; b1.dst[5] = w2pu_self; b1.n4[5] = HO4;
        b1.src[6] = l2_pu_self; b1.dst[6] = w2pu_self; b1.n4[6] = 0;
        cvt_batch_k<<<dim3(cdiv(HH4, 256), 7), 256, 0, s1>>>(b1);
    }

    // ---- projections (fp32 in, CVT path; fp16 out) ----
    gemm_tc<true, false, false, true, true, false><<<dim3(2, GU), 256, SMB, s0>>>(user_x, W_ue, nullptr, nullptr, b_ue, hu, NU, Hdim, DU);
    cudaEventRecord(g_ev[EV_HU], s0);
    gemm_tc<true, false, false, true, true, false><<<dim3(2, GP), 256, SMB, s1>>>(prod_x, W_pe, nullptr, nullptr, b_pe, hp, NPR, Hdim, DU);
    cudaEventRecord(g_ev[EV_HP], s1);

    // ---- CSR builds (s0: eu, s1: ep) ----
    zero_i_k<<<cdiv(NPR, 256), 256, 0, s0>>>(eu_cnt, NPR);
    count_k<<<cdiv(NE, 256), 256, 0, s0>>>(eu_dst, eu_cnt, NE);
    scan_k<<<1, 1024, 0, s0>>>(eu_cnt, NPR, eu_off, eu_cur);
    scatter_k<<<cdiv(NE, 256), 256, 0, s0>>>(eu_src, eu_dst, eu_cur, eu_adj, NE);

    zero_i_k<<<cdiv(NU, 256), 256, 0, s1>>>(ep_cnt, NU);
    count_k<<<cdiv(NE, 256), 256, 0, s1>>>(ep_dst, ep_cnt, NE);
    scan_k<<<1, 1024, 0, s1>>>(ep_cnt, NU, ep_off, ep_cur);
    scatter_k<<<cdiv(NE, 256), 256, 0, s1>>>(ep_src, ep_dst, ep_cur, ep_adj, NE);

    // ---- layer 1, up-chain on s0 (dst = products) ----
    gemm_tc<false, true, false, true, false, false><<<dim3(2, GU), 256, SMB, s0>>>(hu, w1up_pre, nullptr, nullptr, nullptr, m_u, NU, Hdim, Hdim);
    agg_mean_h_k<<<cdiv(NPR * 32, 256), 256, 0, s0>>>(m_u, eu_off, eu_adj, ng_p, NPR);
    cudaStreamWaitEvent(s0, g_ev[EV_HP], 0);
    gemm_tc<false, false, true, true, false, false><<<dim3(2, GP), 256, SMB, s0>>>(hp, w1up_self, ng_p, w1up_nb, nullptr, hp1, NPR, Hdim, Hdim);
    relu_norm_h_k<<<cdiv(NPR * 32, 256), 256, 0, s0>>>(hp1, NPR);
    cudaEventRecord(g_ev[EV_HP1], s0);

    // ---- layer 1, pu-chain on s1 (dst = users) ----
    gemm_tc<false, true, false, true, false, false><<<dim3(2, GP), 256, SMB, s1>>>(hp, w1pu_pre, nullptr, nullptr, nullptr, m_p, NPR, Hdim, Hdim);
    agg_mean_h_k<<<cdiv(NU * 32, 256), 256, 0, s1>>>(m_p, ep_off, ep_adj, ng_u, NU);
    cudaStreamWaitEvent(s1, g_ev[EV_HU], 0);
    gemm_tc<false, false, true, true, false, false><<<dim3(2, GU), 256, SMB, s1>>>(hu, w1pu_self, ng_u, w1pu_nb, nullptr, hu1, NU, Hdim, Hdim);
    relu_norm_h_k<<<cdiv(NU * 32, 256), 256, 0, s1>>>(hu1, NU);
    cudaEventRecord(g_ev[EV_HU1], s1);

    // ---- layer 2, up-chain on s0 (fused norm epilogue, fp32 out) ----
    cudaStreamWaitEvent(s0, g_ev[EV_HU1], 0);
    gemm_tc<false, true, false, true, false, false><<<dim3(2, GU), 256, SMB, s0>>>(hu1, w2up_pre, nullptr, nullptr, nullptr, m_u, NU, Hdim, Hdim);
    agg_mean_h_k<<<cdiv(NPR * 32, 256), 256, 0, s0>>>(m_u, eu_off, eu_adj, ng_p, NPR);
    gemm_tc<false, false, true, false, false, true><<<dim3(1, GP), 256, SMB, s0>>>(hp1, w2up_self, ng_p, w2up_nb, nullptr, hp2, NPR, OUTD, Hdim);

    // ---- layer 2, pu-chain on s1 (fused norm epilogue, fp32 out) ----
    cudaStreamWaitEvent(s1, g_ev[EV_HP1], 0);
    gemm_tc<false, true, false, true, false, false><<<dim3(2, GP), 256, SMB, s1>>>(hp1, w2pu_pre, nullptr, nullptr, nullptr, m_p, NPR, Hdim, Hdim);
    agg_mean_h_k<<<cdiv(NU * 32, 256), 256, 0, s1>>>(m_p, ep_off, ep_adj, ng_u, NU);
    gemm_tc<false, false, true, false, false, true><<<dim3(1, GU), 256, SMB, s1>>>(hu1, w2pu_self, ng_u, w2pu_nb, nullptr, hu2, NU, OUTD, Hdim);
    cudaEventRecord(g_ev[EV_HU2], s1);

    // ---- join + fused pair dots on s0 ----
    cudaStreamWaitEvent(s0, g_ev[EV_HU2], 0);
    pair_dot2_k<<<cdiv(2 * NPAIR * 32, 256), 256, 0, s0>>>(hu2, hp2, pos_u, pos_p, neg_u, neg_p, pos, neg, NPAIR);
}

// round 14
// speedup vs baseline: 1.3512x; 1.0540x over previous
#include <cuda_runtime.h>
#include <cuda_fp16.h>
#include <cstdint>

#define NU   50000
#define NPR  20000
#define DU   128
#define Hdim 256
#define OUTD 128
#define NE   800000
#define NPAIR 200000

// ------------------------- scratch (device globals, no allocs) -------------
__device__ __half g_hu  [(size_t)NU  * Hdim];
__device__ __half g_hp  [(size_t)NPR * Hdim];
__device__ __half g_hu1 [(size_t)NU  * Hdim];
__device__ __half g_hp1 [(size_t)NPR * Hdim];
__device__ __half g_m_u [(size_t)NU  * Hdim];
__device__ __half g_m_p [(size_t)NPR * Hdim];
__device__ __half g_ng_p[(size_t)NPR * Hdim];
__device__ __half g_ng_u[(size_t)NU  * Hdim];

// fp16 copies of the 12 layer weights
__device__ __half g_w_l1up_pre [Hdim * Hdim];
__device__ __half g_w_l1up_nb  [Hdim * Hdim];
__device__ __half g_w_l1up_self[Hdim * Hdim];
__device__ __half g_w_l1pu_pre [Hdim * Hdim];
__device__ __half g_w_l1pu_nb  [Hdim * Hdim];
__device__ __half g_w_l1pu_self[Hdim * Hdim];
__device__ __half g_w_l2up_pre [Hdim * Hdim];
__device__ __half g_w_l2up_nb  [Hdim * OUTD];
__device__ __half g_w_l2up_self[Hdim * OUTD];
__device__ __half g_w_l2pu_pre [Hdim * Hdim];
__device__ __half g_w_l2pu_nb  [Hdim * OUTD];
__device__ __half g_w_l2pu_self[Hdim * OUTD];

__device__ int g_eu_cnt[NPR];
__device__ int g_eu_off[NPR + 1];
__device__ int g_eu_cur[NPR];
__device__ int g_eu_adj[NE];

__device__ int g_ep_cnt[NU];
__device__ int g_ep_off[NU + 1];
__device__ int g_ep_cur[NU];
__device__ int g_ep_adj[NE];

// ---- streams/events created at static init ----
enum { EV_FORK = 0, EV_HP, EV_HU, EV_HP1, EV_HU1, EV_HU2, EV_COUNT };
static cudaStream_t g_s1;
static cudaEvent_t  g_ev[EV_COUNT];
struct InitStreams {
    InitStreams() {
        cudaStreamCreateWithFlags(&g_s1, cudaStreamNonBlocking);
        for (int i = 0; i < EV_COUNT; i++)
            cudaEventCreateWithFlags(&g_ev[i], cudaEventDisableTiming);
    }
};
static InitStreams g_init_streams;

// ------------------------- helpers -----------------------------------------
__device__ __forceinline__ uint32_t pack_h2(float x, float y) {
    __half2 h = __floats2half2_rn(x, y);
    return *reinterpret_cast<uint32_t*>(&h);
}

struct CvtBatch {
    const float* src[7];
    __half*      dst[7];
    int          n4[7];
};
__global__ void cvt_batch_k(CvtBatch b) {
    int y = blockIdx.y;
    int i = blockIdx.x * blockDim.x + threadIdx.x;
    if (i < b.n4[y]) {
        float4 v = reinterpret_cast<const float4*>(b.src[y])[i];
        uint32_t* d = reinterpret_cast<uint32_t*>(b.dst[y] + (size_t)i * 4);
        d[0] = pack_h2(v.x, v.y);
        d[1] = pack_h2(v.z, v.w);
    }
}

// ------------------------- CSR build ---------------------------------------
__global__ void zero_i_k(int* __restrict__ p, int n) {
    int i = blockIdx.x * blockDim.x + threadIdx.x;
    if (i < n) p[i] = 0;
}

__global__ void count_k(const int* __restrict__ dst, int* __restrict__ cnt, int n) {
    int i = blockIdx.x * blockDim.x + threadIdx.x;
    if (i < n) atomicAdd(&cnt[dst[i]], 1);
}

__global__ void scan_k(const int* __restrict__ cnt, int n,
                       int* __restrict__ off, int* __restrict__ cur) {
    __shared__ int sh[1024];
    const int tid = threadIdx.x;
    const int CH = (n + 1023) >> 10;
    const int s = tid * CH;
    const int e = min(s + CH, n);

    int local = 0;
    for (int i = s; i < e; i++) local += cnt[i];
    sh[tid] = local;
    __syncthreads();

    #pragma unroll
    for (int d = 1; d < 1024; d <<= 1) {
        int t = (tid >= d) ? sh[tid - d] : 0;
        __syncthreads();
        sh[tid] += t;
        __syncthreads();
    }
    int excl = sh[tid] - local;
    int total = sh[1023];

    int run = excl;
    for (int i = s; i < e; i++) {
        off[i] = run;
        cur[i] = run;
        run += cnt[i];
    }
    if (tid == 0) off[n] = total;
}

__global__ void scatter_k(const int* __restrict__ src, const int* __restrict__ dst,
                          int* __restrict__ cur, int* __restrict__ adj, int n) {
    int i = blockIdx.x * blockDim.x + threadIdx.x;
    if (i < n) {
        int pos = atomicAdd(&cur[dst[i]], 1);
        adj[pos] = src[i];
    }
}

// ------------------------- FP16 tensor-core GEMM ---------------------------
// 128x128 tile, 256 thr = 8 warps (2m x 4n), warp tile 64x32.
// CVT=true : fp32 A/B, BK=32, register-staged 2-stage loader (projections).
// CVT=false: fp16 A/B, BK=64, cp.async 3-stage pipeline (heavy GEMMs).
// mma.sync.m16n8k16; A via ldmatrix.x4, B via ldmatrix.x4.trans.
// OUTF16: __half C. NORM: fused relu+row-L2-norm (N==128, grid.x==1, fp32 C).
#define CK 32                 // CVT-path k-slab
#define CA_LDH 40             // 80B ≡ 16 mod 128 -> conflict-free
#define CB_LDH 136            // 272B ≡ 16 mod 128
#define CA_STG (128 * CA_LDH)
#define CB_STG (CK * CB_LDH)

#define HK 64                 // heavy-path k-slab
#define HA_LDH 72             // 144B ≡ 16 mod 128 -> conflict-free
#define HB_LDH 136
#define HA_STG (128 * HA_LDH)
#define HB_STG (HK * HB_LDH)
#define HNST 3
#define GEMM_SMEM_BYTES (HNST * (HA_STG + HB_STG) * 2)   // 107.5 KB

__device__ __forceinline__ void mma_f16(float c[4], uint32_t a0, uint32_t a1,
                                        uint32_t a2, uint32_t a3,
                                        uint32_t b0, uint32_t b1) {
    asm volatile(
        "mma.sync.aligned.m16n8k16.row.col.f32.f16.f16.f32 "
        "{%0,%1,%2,%3}, {%4,%5,%6,%7}, {%8,%9}, {%0,%1,%2,%3};\n"
        : "+f"(c[0]), "+f"(c[1]), "+f"(c[2]), "+f"(c[3])
        : "r"(a0), "r"(a1), "r"(a2), "r"(a3), "r"(b0), "r"(b1));
}

__device__ __forceinline__ void ldsm_x4(uint32_t f[4], uint32_t saddr) {
    asm volatile("ldmatrix.sync.aligned.m8n8.x4.shared.b16 {%0,%1,%2,%3}, [%4];"
                 : "=r"(f[0]), "=r"(f[1]), "=r"(f[2]), "=r"(f[3]) : "r"(saddr));
}
__device__ __forceinline__ void ldsm_x4_t(uint32_t f[4], uint32_t saddr) {
    asm volatile("ldmatrix.sync.aligned.m8n8.x4.trans.shared.b16 {%0,%1,%2,%3}, [%4];"
                 : "=r"(f[0]), "=r"(f[1]), "=r"(f[2]), "=r"(f[3]) : "r"(saddr));
}

template <bool BIAS, bool RELU, bool DUAL, bool OUTF16, bool CVT, bool NORM>
__global__ void __launch_bounds__(256, 2)
gemm_tc(const void* __restrict__ A0v, const void* __restrict__ B0v,
        const void* __restrict__ A1v, const void* __restrict__ B1v,
        const float* __restrict__ bias, void* __restrict__ Cv,
        int M, int N, int K) {
    extern __shared__ __half smh[];

    const int bm = blockIdx.y * 128;
    const int bn = blockIdx.x * 128;
    const int tid  = threadIdx.x;
    const int lane = tid & 31;
    const int warp = tid >> 5;
    const int g = lane >> 2;
    const int t = lane & 3;
    const int wm = (warp & 1) * 64;
    const int wn = (warp >> 1) * 32;

    const int a_row = lane & 15;
    const int a_colh = (lane >> 4) * 8;
    const int b_row = ((lane >> 3) & 1) * 8 + (lane & 7);
    const int b_colh = (lane >> 4) * 8;

    float acc[4][4][4];
    #pragma unroll
    for (int i = 0; i < 4; i++)
        #pragma unroll
        for (int j = 0; j < 4; j++)
            #pragma unroll
            for (int r = 0; r < 4; r++) acc[i][j][r] = 0.f;

    // one k16 step of fragment loads + MMAs at smem strides (alh, blh)
    auto step_k16 = [&](const __half* Asb, const __half* Bsb, int ko, int alh, int blh) {
        const uint32_t a_base = (uint32_t)__cvta_generic_to_shared(
            Asb + (wm + a_row) * alh + ko + a_colh);
        uint32_t af[4][4];
        #pragma unroll
        for (int mt = 0; mt < 4; mt++)
            ldsm_x4(af[mt], a_base + (uint32_t)(mt * 16 * alh * 2));
        uint32_t bq[2][4];
        #pragma unroll
        for (int nb = 0; nb < 2; nb++) {
            uint32_t b_base = (uint32_t)__cvta_generic_to_shared(
                Bsb + (ko + b_row) * blh + wn + nb * 16 + b_colh);
            ldsm_x4_t(bq[nb], b_base);
        }
        #pragma unroll
        for (int mt = 0; mt < 4; mt++)
            #pragma unroll
            for (int nt = 0; nt < 4; nt++) {
                const int nb = nt >> 1, sub = (nt & 1) * 2;
                mma_f16(acc[mt][nt], af[mt][0], af[mt][1], af[mt][2], af[mt][3],
                        bq[nb][sub], bq[nb][sub + 1]);
            }
    };

    if constexpr (!CVT) {
        // ---- fp16 inputs, BK=64, cp.async 3-stage pipeline ----
        const int tps = K / HK;
        const int ntiles = (DUAL ? 2 : 1) * tps;
        auto issue = [&](int tix) {
            if (tix < ntiles) {
                const __half* A = (const __half*)A0v;
                const __half* B = (const __half*)B0v;
                int k0 = tix;
                if (DUAL && tix >= tps) { A = (const __half*)A1v; B = (const __half*)B1v; k0 -= tps; }
                k0 *= HK;
                __half* Asb = smh + (tix % HNST) * HA_STG;
                __half* Bsb = smh + HNST * HA_STG + (tix % HNST) * HB_STG;
                #pragma unroll
                for (int i = 0; i < 4; i++) {
                    int idx = tid + i * 256;        // 1024 chunks: 128 rows x 8
                    int r = idx >> 3;
                    int c = idx & 7;
                    int rr = (bm + r < M) ? (bm + r) : (M - 1);
                    int sz = (bm + r < M) ? 16 : 0;
                    const __half* src = A + (size_t)rr * K + k0 + c * 8;
                    uint32_t dst = (uint32_t)__cvta_generic_to_shared(Asb + r * HA_LDH + c * 8);
                    asm volatile("cp.async.cg.shared.global [%0], [%1], 16, %2;\n"
                                 :: "r"(dst), "l"(src), "r"(sz));
                }
                #pragma unroll
                for (int i = 0; i < 4; i++) {
                    int idx = tid + i * 256;        // 1024 chunks: 64 rows x 16
                    int r = idx >> 4;
                    int c = idx & 15;
                    const __half* src = B + (size_t)(k0 + r) * N + bn + c * 8;
                    uint32_t dst = (uint32_t)__cvta_generic_to_shared(Bsb + r * HB_LDH + c * 8);
                    asm volatile("cp.async.cg.shared.global [%0], [%1], 16;\n"
                                 :: "r"(dst), "l"(src));
                }
            }
            asm volatile("cp.async.commit_group;\n" ::: "memory");
        };

        issue(0);
        issue(1);
        for (int tix = 0; tix < ntiles; tix++) {
            asm volatile("cp.async.wait_group 1;\n" ::: "memory");
            __syncthreads();
            issue(tix + 2);
            const __half* Asb = smh + (tix % HNST) * HA_STG;
            const __half* Bsb = smh + HNST * HA_STG + (tix % HNST) * HB_STG;
            #pragma unroll
            for (int kk = 0; kk < 4; kk++)
                step_k16(Asb, Bsb, kk * 16, HA_LDH, HB_LDH);
        }
    } else {
        // ---- fp32 inputs, BK=32, register-staged 2-stage loader ----
        const int ntiles = K / CK;
        float4 ar[4], br[4];
        auto load_tile = [&](int tix) {
            const float* A = (const float*)A0v;
            const float* B = (const float*)B0v;
            int k0 = tix * CK;
            #pragma unroll
            for (int i = 0; i < 4; i++) {
                int idx = tid + i * 256;
                int r = idx >> 3;
                int c = idx & 7;
                ar[i] = make_float4(0.f, 0.f, 0.f, 0.f);
                if (bm + r < M)
                    ar[i] = *reinterpret_cast<const float4*>(A + (size_t)(bm + r) * K + k0 + c * 4);
            }
            #pragma unroll
            for (int i = 0; i < 4; i++) {
                int idx = tid + i * 256;
                int r = idx >> 5;
                int c = idx & 31;
                br[i] = *reinterpret_cast<const float4*>(B + (size_t)(k0 + r) * N + bn + c * 4);
            }
        };
        auto store_tile = [&](int buf) {
            __half* Asb = smh + buf * CA_STG;
            __half* Bsb = smh + 2 * CA_STG + buf * CB_STG;
            #pragma unroll
            for (int i = 0; i < 4; i++) {
                int idx = tid + i * 256;
                int r = idx >> 3;
                int c = idx & 7;
                uint32_t* p = reinterpret_cast<uint32_t*>(Asb + r * CA_LDH + c * 4);
                p[0] = pack_h2(ar[i].x, ar[i].y);
                p[1] = pack_h2(ar[i].z, ar[i].w);
            }
            #pragma unroll
            for (int i = 0; i < 4; i++) {
                int idx = tid + i * 256;
                int r = idx >> 5;
                int c = idx & 31;
                uint32_t* p = reinterpret_cast<uint32_t*>(Bsb + r * CB_LDH + c * 4);
                p[0] = pack_h2(br[i].x, br[i].y);
                p[1] = pack_h2(br[i].z, br[i].w);
            }
        };

        load_tile(0);
        store_tile(0);
        __syncthreads();
        for (int tix = 0; tix < ntiles; tix++) {
            const int buf = tix & 1;
            if (tix + 1 < ntiles) load_tile(tix + 1);
            const __half* Asb = smh + buf * CA_STG;
            const __half* Bsb = smh + 2 * CA_STG + buf * CB_STG;
            #pragma unroll
            for (int kk = 0; kk < 2; kk++)
                step_k16(Asb, Bsb, kk * 16, CA_LDH, CB_LDH);
            if (tix + 1 < ntiles) {
                store_tile(buf ^ 1);
                __syncthreads();
            }
        }
    }

    if constexpr (NORM) {
        __syncthreads();
        float* rowsum = reinterpret_cast<float*>(smh);   // [128][4]
        const int nw = warp >> 1;
        const int mh = warp & 1;

        float part[4][2];
        #pragma unroll
        for (int mt = 0; mt < 4; mt++) {
            part[mt][0] = 0.f; part[mt][1] = 0.f;
            #pragma unroll
            for (int nt = 0; nt < 4; nt++) {
                #pragma unroll
                for (int h = 0; h < 2; h++) {
                    float vx = fmaxf(acc[mt][nt][h * 2 + 0], 0.f);
                    float vy = fmaxf(acc[mt][nt][h * 2 + 1], 0.f);
                    part[mt][h] += vx * vx + vy * vy;
                }
            }
        }
        #pragma unroll
        for (int mt = 0; mt < 4; mt++)
            #pragma unroll
            for (int h = 0; h < 2; h++) {
                part[mt][h] += __shfl_xor_sync(0xFFFFFFFFu, part[mt][h], 1);
                part[mt][h] += __shfl_xor_sync(0xFFFFFFFFu, part[mt][h], 2);
            }
        if (t == 0) {
            #pragma unroll
            for (int mt = 0; mt < 4; mt++)
                #pragma unroll
                for (int h = 0; h < 2; h++) {
                    int row = mh * 64 + mt * 16 + h * 8 + g;
                    rowsum[row * 4 + nw] = part[mt][h];
                }
        }
        __syncthreads();

        float* C = (float*)Cv;
        #pragma unroll
        for (int mt = 0; mt < 4; mt++) {
            #pragma unroll
            for (int h = 0; h < 2; h++) {
                int lrow = mh * 64 + mt * 16 + h * 8 + g;
                int r = bm + lrow;
                if (r >= M) continue;
                float s = rowsum[lrow * 4 + 0] + rowsum[lrow * 4 + 1]
                        + rowsum[lrow * 4 + 2] + rowsum[lrow * 4 + 3];
                float inv = (s > 0.f) ? rsqrtf(s) : 1.f;
                #pragma unroll
                for (int nt = 0; nt < 4; nt++) {
                    int col = wn + nt * 8 + t * 2;
                    float vx = fmaxf(acc[mt][nt][h * 2 + 0], 0.f) * inv;
                    float vy = fmaxf(acc[mt][nt][h * 2 + 1], 0.f) * inv;
                    *reinterpret_cast<float2*>(C + (size_t)r * N + col) = make_float2(vx, vy);
                }
            }
        }
        return;
    }

    // ---- standard epilogue ----
    #pragma unroll
    for (int mt = 0; mt < 4; mt++) {
        int r0 = bm + wm + mt * 16 + g;
        #pragma unroll
        for (int nt = 0; nt < 4; nt++) {
            int col = bn + wn + nt * 8 + t * 2;
            float b0 = 0.f, b1 = 0.f;
            if (BIAS) { b0 = bias[col]; b1 = bias[col + 1]; }
            #pragma unroll
            for (int h = 0; h < 2; h++) {
                int r = r0 + h * 8;
                if (r >= M) continue;
                float vx = acc[mt][nt][h * 2 + 0] + b0;
                float vy = acc[mt][nt][h * 2 + 1] + b1;
                if (RELU) { vx = fmaxf(vx, 0.f); vy = fmaxf(vy, 0.f); }
                if (OUTF16) {
                    __half* C = (__half*)Cv;
                    *reinterpret_cast<uint32_t*>(C + (size_t)r * N + col) = pack_h2(vx, vy);
                } else {
                    float* C = (float*)Cv;
                    *reinterpret_cast<float2*>(C + (size_t)r * N + col) = make_float2(vx, vy);
                }
            }
        }
    }
}

// ------------------------- mean aggregation (fp16 in, fp16 out) ------------
__global__ void agg_mean_h_k(const __half* __restrict__ feat,
                             const int* __restrict__ off, const int* __restrict__ adj,
                             __half* __restrict__ out, int n_dst) {
    int w    = (blockIdx.x * blockDim.x + threadIdx.x) >> 5;
    int lane = threadIdx.x & 31;
    if (w >= n_dst) return;
    int s = off[w], e = off[w + 1];
    float acc[8] = {};
    const size_t loff = (size_t)lane * 8;

    auto accum = [&](uint4 v) {
        const uint32_t u[4] = {v.x, v.y, v.z, v.w};
        #pragma unroll
        for (int j = 0; j < 4; j++) {
            float2 f = __half22float2(*reinterpret_cast<const __half2*>(&u[j]));
            acc[j * 2 + 0] += f.x;
            acc[j * 2 + 1] += f.y;
        }
    };

    int i = s;
    for (; i + 1 < e; i += 2) {
        int s0 = adj[i], s1 = adj[i + 1];
        uint4 v0 = *reinterpret_cast<const uint4*>(feat + (size_t)s0 * Hdim + loff);
        uint4 v1 = *reinterpret_cast<const uint4*>(feat + (size_t)s1 * Hdim + loff);
        accum(v0);
        accum(v1);
    }
    if (i < e) {
        accum(*reinterpret_cast<const uint4*>(feat + (size_t)adj[i] * Hdim + loff));
    }

    float inv = 1.f / fmaxf((float)(e - s), 1.f);
    uint4 o;
    uint32_t* ow = reinterpret_cast<uint32_t*>(&o);
    #pragma unroll
    for (int j = 0; j < 4; j++)
        ow[j] = pack_h2(acc[j * 2] * inv, acc[j * 2 + 1] * inv);
    *reinterpret_cast<uint4*>(out + (size_t)w * Hdim + loff) = o;
}

// ------------------------- relu + row L2-normalize (fp16, in place) --------
__global__ void relu_norm_h_k(__half* __restrict__ buf, int n) {
    int w    = (blockIdx.x * blockDim.x + threadIdx.x) >> 5;
    int lane = threadIdx.x & 31;
    if (w >= n) return;
    __half* row = buf + (size_t)w * Hdim;
    uint4 v = *reinterpret_cast<const uint4*>(row + lane * 8);
    uint32_t* vw = reinterpret_cast<uint32_t*>(&v);
    float f[8];
    float s = 0.f;
    #pragma unroll
    for (int j = 0; j < 4; j++) {
        float2 p = __half22float2(*reinterpret_cast<const __half2*>(&vw[j]));
        f[j * 2 + 0] = fmaxf(p.x, 0.f);
        f[j * 2 + 1] = fmaxf(p.y, 0.f);
        s += f[j * 2] * f[j * 2] + f[j * 2 + 1] * f[j * 2 + 1];
    }
    #pragma unroll
    for (int o = 16; o; o >>= 1) s += __shfl_xor_sync(0xFFFFFFFFu, s, o);
    float inv = (s > 0.f) ? rsqrtf(s) : 1.f;
    #pragma unroll
    for (int j = 0; j < 4; j++)
        vw[j] = pack_h2(f[j * 2] * inv, f[j * 2 + 1] * inv);
    *reinterpret_cast<uint4*>(row + lane * 8) = v;
}

// ------------------------- pair cosine dots (pos+neg fused) ----------------
__global__ void pair_dot2_k(const float* __restrict__ xu, const float* __restrict__ xp,
                            const int* __restrict__ pu, const int* __restrict__ pp,
                            const int* __restrict__ nu, const int* __restrict__ np,
                            float* __restrict__ pos, float* __restrict__ neg, int n) {
    int w    = (blockIdx.x * blockDim.x + threadIdx.x) >> 5;
    int lane = threadIdx.x & 31;
    if (w >= 2 * n) return;
    bool isneg = (w >= n);
    int idx = isneg ? (w - n) : w;
    int u = isneg ? nu[idx] : pu[idx];
    int p = isneg ? np[idx] : pp[idx];
    float4 a = reinterpret_cast<const float4*>(xu + (size_t)u * OUTD)[lane];
    float4 b = reinterpret_cast<const float4*>(xp + (size_t)p * OUTD)[lane];
    float s = a.x * b.x + a.y * b.y + a.z * b.z + a.w * b.w;
    #pragma unroll
    for (int o = 16; o; o >>= 1) s += __shfl_xor_sync(0xFFFFFFFFu, s, o);
    if (lane == 0) {
        if (isneg) neg[idx] = s; else pos[idx] = s;
    }
}

// ------------------------- launch ------------------------------------------
static inline int cdiv(int a, int b) { return (a + b - 1) / b; }

extern "C" void kernel_launch(void* const* d_in, const int* in_sizes, int n_in,
                              void* d_out, int out_size) {
    const float* user_x = (const float*)d_in[0];
    const float* prod_x = (const float*)d_in[1];
    const float* W_ue   = (const float*)d_in[2];
    const float* b_ue   = (const float*)d_in[3];
    const float* W_pe   = (const float*)d_in[4];
    const float* b_pe   = (const float*)d_in[5];
    const float* l1_up_pre  = (const float*)d_in[6];
    const float* l1_up_nb   = (const float*)d_in[7];
    const float* l1_up_self = (const float*)d_in[8];
    const float* l1_pu_pre  = (const float*)d_in[9];
    const float* l1_pu_nb   = (const float*)d_in[10];
    const float* l1_pu_self = (const float*)d_in[11];
    const float* l2_up_pre  = (const float*)d_in[12];
    const float* l2_up_nb   = (const float*)d_in[13];
    const float* l2_up_self = (const float*)d_in[14];
    const float* l2_pu_pre  = (const float*)d_in[15];
    const float* l2_pu_nb   = (const float*)d_in[16];
    const float* l2_pu_self = (const float*)d_in[17];
    const int* eu_src = (const int*)d_in[18];
    const int* eu_dst = (const int*)d_in[19];
    const int* ep_src = (const int*)d_in[20];
    const int* ep_dst = (const int*)d_in[21];
    const int* pos_u  = (const int*)d_in[22];
    const int* pos_p  = (const int*)d_in[23];
    const int* neg_u  = (const int*)d_in[24];
    const int* neg_p  = (const int*)d_in[25];

    __half *hu, *hp, *hu1, *hp1, *m_u, *m_p, *ng_p, *ng_u;
    __half *w1up_pre, *w1up_nb, *w1up_self, *w1pu_pre, *w1pu_nb, *w1pu_self;
    __half *w2up_pre, *w2up_nb, *w2up_self, *w2pu_pre, *w2pu_nb, *w2pu_self;
    int *eu_cnt, *eu_off, *eu_cur, *eu_adj;
    int *ep_cnt, *ep_off, *ep_cur, *ep_adj;
    cudaGetSymbolAddress((void**)&hu,   g_hu);
    cudaGetSymbolAddress((void**)&hp,   g_hp);
    cudaGetSymbolAddress((void**)&hu1,  g_hu1);
    cudaGetSymbolAddress((void**)&hp1,  g_hp1);
    cudaGetSymbolAddress((void**)&m_u,  g_m_u);
    cudaGetSymbolAddress((void**)&m_p,  g_m_p);
    cudaGetSymbolAddress((void**)&ng_p, g_ng_p);
    cudaGetSymbolAddress((void**)&ng_u, g_ng_u);
    cudaGetSymbolAddress((void**)&w1up_pre,  g_w_l1up_pre);
    cudaGetSymbolAddress((void**)&w1up_nb,   g_w_l1up_nb);
    cudaGetSymbolAddress((void**)&w1up_self, g_w_l1up_self);
    cudaGetSymbolAddress((void**)&w1pu_pre,  g_w_l1pu_pre);
    cudaGetSymbolAddress((void**)&w1pu_nb,   g_w_l1pu_nb);
    cudaGetSymbolAddress((void**)&w1pu_self, g_w_l1pu_self);
    cudaGetSymbolAddress((void**)&w2up_pre,  g_w_l2up_pre);
    cudaGetSymbolAddress((void**)&w2up_nb,   g_w_l2up_nb);
    cudaGetSymbolAddress((void**)&w2up_self, g_w_l2up_self);
    cudaGetSymbolAddress((void**)&w2pu_pre,  g_w_l2pu_pre);
    cudaGetSymbolAddress((void**)&w2pu_nb,   g_w_l2pu_nb);
    cudaGetSymbolAddress((void**)&w2pu_self, g_w_l2pu_self);
    cudaGetSymbolAddress((void**)&eu_cnt, g_eu_cnt);
    cudaGetSymbolAddress((void**)&eu_off, g_eu_off);
    cudaGetSymbolAddress((void**)&eu_cur, g_eu_cur);
    cudaGetSymbolAddress((void**)&eu_adj, g_eu_adj);
    cudaGetSymbolAddress((void**)&ep_cnt, g_ep_cnt);
    cudaGetSymbolAddress((void**)&ep_off, g_ep_off);
    cudaGetSymbolAddress((void**)&ep_cur, g_ep_cur);
    cudaGetSymbolAddress((void**)&ep_adj, g_ep_adj);

    cudaFuncSetAttribute(gemm_tc<true,  false, false, true,  true,  false>,
                         cudaFuncAttributeMaxDynamicSharedMemorySize, GEMM_SMEM_BYTES);
    cudaFuncSetAttribute(gemm_tc<false, true,  false, true,  false, false>,
                         cudaFuncAttributeMaxDynamicSharedMemorySize, GEMM_SMEM_BYTES);
    cudaFuncSetAttribute(gemm_tc<false, false, true,  true,  false, false>,
                         cudaFuncAttributeMaxDynamicSharedMemorySize, GEMM_SMEM_BYTES);
    cudaFuncSetAttribute(gemm_tc<false, false, true,  false, false, true>,
                         cudaFuncAttributeMaxDynamicSharedMemorySize, GEMM_SMEM_BYTES);

    float* out = (float*)d_out;
    float* hu2 = out;
    float* hp2 = out + (size_t)NU * OUTD;
    float* pos = hp2 + (size_t)NPR * OUTD;
    float* neg = pos + NPAIR;

    cudaStream_t s0 = 0;
    cudaStream_t s1 = g_s1;

    const int GU = cdiv(NU, 128), GP = cdiv(NPR, 128);
    const int SMB = GEMM_SMEM_BYTES;
    const int HH4 = Hdim * Hdim / 4, HO4 = Hdim * OUTD / 4;

    // ---- fork ----
    cudaEventRecord(g_ev[EV_FORK], s0);
    cudaStreamWaitEvent(s1, g_ev[EV_FORK], 0);

    // ---- fused weight fp16 conversion: one launch per stream ----
    {
        CvtBatch b0;
        b0.src[0] = l1_up_pre;  b0.dst[0] = w1up_pre;  b0.n4[0] = HH4;
        b0.src[1] = l1_up_nb;   b0.dst[1] = w1up_nb;   b0.n4[1] = HH4;
        b0.src[2] = l1_up_self; b0.dst[2] = w1up_self; b0.n4[2] = HH4;
        b0.src[3] = l2_up_pre;  b0.dst[3] = w2up_pre;  b0.n4[3] = HH4;
        b0.src[4] = l2_up_nb;   b0.dst[4] = w2up_nb;   b0.n4[4] = HO4;
        b0.src[5] = l2_up_self; b0.dst[5] = w2up_self; b0.n4[5] = HO4;
        b0.src[6] = l2_up_self; b0.dst[6] = w2up_self; b0.n4[6] = 0;
        cvt_batch_k<<<dim3(cdiv(HH4, 256), 7), 256, 0, s0>>>(b0);

        CvtBatch b1;
        b1.src[0] = l1_pu_pre;  b1.dst[0] = w1pu_pre;  b1.n4[0] = HH4;
        b1.src[1] = l1_pu_nb;   b1.dst[1] = w1pu_nb;   b1.n4[1] = HH4;
        b1.src[2] = l1_pu_self; b1.dst[2] = w1pu_self; b1.n4[2] = HH4;
        b1.src[3] = l2_pu_pre;  b1.dst[3] = w2pu_pre;  b1.n4[3] = HH4;
        b1.src[4] = l2_pu_nb;   b1.dst[4] = w2pu_nb;   b1.n4[4] = HO4;
        b1.src[5] = l2_pu_self; b1.dst[5] = w2pu_self; b1.n4[5] = HO4;
        b1.src[6] = l2_pu_self; b1.dst[6] = w2pu_self; b1.n4[6] = 0;
        cvt_batch_k<<<dim3(cdiv(HH4, 256), 7), 256, 0, s1>>>(b1);
    }

    // ---- projections (fp32 in, CVT path; fp16 out) ----
    gemm_tc<true, false, false, true, true, false><<<dim3(2, GU), 256, SMB, s0>>>(user_x, W_ue, nullptr, nullptr, b_ue, hu, NU, Hdim, DU);
    cudaEventRecord(g_ev[EV_HU], s0);
    gemm_tc<true, false, false, true, true, false><<<dim3(2, GP), 256, SMB, s1>>>(prod_x, W_pe, nullptr, nullptr, b_pe, hp, NPR, Hdim, DU);
    cudaEventRecord(g_ev[EV_HP], s1);

    // ---- CSR builds (s0: eu, s1: ep) ----
    zero_i_k<<<cdiv(NPR, 256), 256, 0, s0>>>(eu_cnt, NPR);
    count_k<<<cdiv(NE, 256), 256, 0, s0>>>(eu_dst, eu_cnt, NE);
    scan_k<<<1, 1024, 0, s0>>>(eu_cnt, NPR, eu_off, eu_cur);
    scatter_k<<<cdiv(NE, 256), 256, 0, s0>>>(eu_src, eu_dst, eu_cur, eu_adj, NE);

    zero_i_k<<<cdiv(NU, 256), 256, 0, s1>>>(ep_cnt, NU);
    count_k<<<cdiv(NE, 256), 256, 0, s1>>>(ep_dst, ep_cnt, NE);
    scan_k<<<1, 1024, 0, s1>>>(ep_cnt, NU, ep_off, ep_cur);
    scatter_k<<<cdiv(NE, 256), 256, 0, s1>>>(ep_src, ep_dst, ep_cur, ep_adj, NE);

    // ---- layer 1, up-chain on s0 (dst = products) ----
    gemm_tc<false, true, false, true, false, false><<<dim3(2, GU), 256, SMB, s0>>>(hu, w1up_pre, nullptr, nullptr, nullptr, m_u, NU, Hdim, Hdim);
    agg_mean_h_k<<<cdiv(NPR * 32, 256), 256, 0, s0>>>(m_u, eu_off, eu_adj, ng_p, NPR);
    cudaStreamWaitEvent(s0, g_ev[EV_HP], 0);
    gemm_tc<false, false, true, true, false, false><<<dim3(2, GP), 256, SMB, s0>>>(hp, w1up_self, ng_p, w1up_nb, nullptr, hp1, NPR, Hdim, Hdim);
    relu_norm_h_k<<<cdiv(NPR * 32, 256), 256, 0, s0>>>(hp1, NPR);
    cudaEventRecord(g_ev[EV_HP1], s0);

    // ---- layer 1, pu-chain on s1 (dst = users) ----
    gemm_tc<false, true, false, true, false, false><<<dim3(2, GP), 256, SMB, s1>>>(hp, w1pu_pre, nullptr, nullptr, nullptr, m_p, NPR, Hdim, Hdim);
    agg_mean_h_k<<<cdiv(NU * 32, 256), 256, 0, s1>>>(m_p, ep_off, ep_adj, ng_u, NU);
    cudaStreamWaitEvent(s1, g_ev[EV_HU], 0);
    gemm_tc<false, false, true, true, false, false><<<dim3(2, GU), 256, SMB, s1>>>(hu, w1pu_self, ng_u, w1pu_nb, nullptr, hu1, NU, Hdim, Hdim);
    relu_norm_h_k<<<cdiv(NU * 32, 256), 256, 0, s1>>>(hu1, NU);
    cudaEventRecord(g_ev[EV_HU1], s1);

    // ---- layer 2, up-chain on s0 (fused norm epilogue, fp32 out) ----
    cudaStreamWaitEvent(s0, g_ev[EV_HU1], 0);
    gemm_tc<false, true, false, true, false, false><<<dim3(2, GU), 256, SMB, s0>>>(hu1, w2up_pre, nullptr, nullptr, nullptr, m_u, NU, Hdim, Hdim);
    agg_mean_h_k<<<cdiv(NPR * 32, 256), 256, 0, s0>>>(m_u, eu_off, eu_adj, ng_p, NPR);
    gemm_tc<false, false, true, false, false, true><<<dim3(1, GP), 256, SMB, s0>>>(hp1, w2up_self, ng_p, w2up_nb, nullptr, hp2, NPR, OUTD, Hdim);

    // ---- layer 2, pu-chain on s1 (fused norm epilogue, fp32 out) ----
    cudaStreamWaitEvent(s1, g_ev[EV_HP1], 0);
    gemm_tc<false, true, false, true, false, false><<<dim3(2, GP), 256, SMB, s1>>>(hp1, w2pu_pre, nullptr, nullptr, nullptr, m_p, NPR, Hdim, Hdim);
    agg_mean_h_k<<<cdiv(NU * 32, 256), 256, 0, s1>>>(m_p, ep_off, ep_adj, ng_u, NU);
    gemm_tc<false, false, true, false, false, true><<<dim3(1, GU), 256, SMB, s1>>>(hu1, w2pu_self, ng_u, w2pu_nb, nullptr, hu2, NU, OUTD, Hdim);
    cudaEventRecord(g_ev[EV_HU2], s1);

    // ---- join + fused pair dots on s0 ----
    cudaStreamWaitEvent(s0, g_ev[EV_HU2], 0);
    pair_dot2_k<<<cdiv(2 * NPAIR * 32, 256), 256, 0, s0>>>(hu2, hp2, pos_u, pos_p, neg_u, neg_p, pos, neg, NPAIR);
}